// round 11
// baseline (speedup 1.0000x reference)
#include <cuda_runtime.h>
#include <cuda_fp16.h>
#include <cstdint>

#define BB 2
#define TT 2048
#define DD 768
#define HH 12
#define DH 64
#define BT (BB*TT)

// ---------------- scratch (static device arrays; no allocation) ----------------
__device__ float  g_proj[(size_t)BT * DD];
__device__ float  g_n   [(size_t)BT * DD];
__device__ float  g_m   [(size_t)BT * DD];
__device__ __half g_xh   [(size_t)BT * DD];
__device__ __half g_qkvh [(size_t)BT * 2304];
__device__ __half g_attnh[(size_t)BT * DD];
__device__ __half g_nh   [(size_t)BT * DD];
__device__ __half g_h1h  [(size_t)BT * 3072];
// transposed fp16 weights [N][K]
__device__ __half g_wqkvTh [(size_t)2304 * 768];
__device__ __half g_wprojTh[(size_t)768 * 768];
__device__ __half g_wfcTh  [(size_t)3072 * 768];
__device__ __half g_woutTh [(size_t)768 * 3072];

__device__ __forceinline__ void mma_f16(float* c, const unsigned* a, const unsigned* b) {
    asm volatile(
        "mma.sync.aligned.m16n8k16.row.col.f32.f16.f16.f32 "
        "{%0,%1,%2,%3}, {%4,%5,%6,%7}, {%8,%9}, {%0,%1,%2,%3};"
        : "+f"(c[0]), "+f"(c[1]), "+f"(c[2]), "+f"(c[3])
        : "r"(a[0]), "r"(a[1]), "r"(a[2]), "r"(a[3]), "r"(b[0]), "r"(b[1]));
}

__device__ __forceinline__ void ldsm_x4(unsigned& r0, unsigned& r1, unsigned& r2, unsigned& r3,
                                        const __half* p) {
    unsigned addr = (unsigned)__cvta_generic_to_shared(p);
    asm volatile("ldmatrix.sync.aligned.m8n8.x4.shared.b16 {%0,%1,%2,%3}, [%4];"
                 : "=r"(r0), "=r"(r1), "=r"(r2), "=r"(r3) : "r"(addr));
}

__device__ __forceinline__ void ldsm_x4_t(unsigned& r0, unsigned& r1, unsigned& r2, unsigned& r3,
                                          const __half* p) {
    unsigned addr = (unsigned)__cvta_generic_to_shared(p);
    asm volatile("ldmatrix.sync.aligned.m8n8.x4.trans.shared.b16 {%0,%1,%2,%3}, [%4];"
                 : "=r"(r0), "=r"(r1), "=r"(r2), "=r"(r3) : "r"(addr));
}

__device__ __forceinline__ unsigned h2pack(float a, float b) {
    __half2 h = __floats2half2_rn(a, b);
    return *reinterpret_cast<unsigned*>(&h);
}

// ---------------- fp16 tensor-core GEMM, 4-stage cp.async + ldmatrix ------------
// C[M,N] = Ah[M,K] @ Bh[N,K]^T + bias, optional GELU, fp32 or fp16 output.
// BM=128 BN=128 BK=32, 256 threads = 8 warps (2x4), warp tile 64x32.
// Prefetch distance 3 (wait_group 2).
#define AH_STR 40
#define AH_SZ (128 * AH_STR)
#define STGH (2 * AH_SZ)
#define N_STG 4
#define GEMMH_SMEM (N_STG * STGH * 2)   // 81920 B

__global__ __launch_bounds__(256)
void gemm_h(const __half* __restrict__ Ah, const __half* __restrict__ Bh,
            const float* __restrict__ bias, void* __restrict__ Cv,
            int M, int N, int K, int do_gelu, int out_half)
{
    extern __shared__ __half smh[];

    const int tid  = threadIdx.x;
    const int wid  = tid >> 5;
    const int lane = tid & 31;
    const int gid  = lane >> 2;
    const int tig  = lane & 3;
    const int wm   = wid >> 2;
    const int wn   = wid & 3;
    const int row0 = blockIdx.y * 128;
    const int col0 = blockIdx.x * 128;

    const int a_r  = (lane & 15);
    const int a_c  = (lane >> 4) * 8;
    const int b_r  = ((lane >> 4) & 1) * 8 + (lane & 7);
    const int b_c  = ((lane >> 3) & 1) * 8;

    float acc[4][4][4];
#pragma unroll
    for (int mt = 0; mt < 4; mt++)
#pragma unroll
        for (int nt = 0; nt < 4; nt++)
#pragma unroll
            for (int c = 0; c < 4; c++) acc[mt][nt][c] = 0.f;

    const int KT = K >> 5;

    auto ld_stage = [&](int s, int k0) {
        __half* As = smh + s * STGH;
        __half* Bs = As + AH_SZ;
#pragma unroll
        for (int l = 0; l < 2; l++) {
            int ci = tid + l * 256;
            int r  = ci >> 2;
            int cc = (ci & 3) * 8;
            unsigned dst = (unsigned)__cvta_generic_to_shared(&As[r * AH_STR + cc]);
            const __half* src = &Ah[(size_t)(row0 + r) * K + k0 + cc];
            asm volatile("cp.async.cg.shared.global [%0], [%1], 16;\n" :: "r"(dst), "l"(src));
        }
#pragma unroll
        for (int l = 0; l < 2; l++) {
            int ci = tid + l * 256;
            int r  = ci >> 2;
            int cc = (ci & 3) * 8;
            unsigned dst = (unsigned)__cvta_generic_to_shared(&Bs[r * AH_STR + cc]);
            const __half* src = &Bh[(size_t)(col0 + r) * K + k0 + cc];
            asm volatile("cp.async.cg.shared.global [%0], [%1], 16;\n" :: "r"(dst), "l"(src));
        }
    };

    // prologue: 3 stages in flight
    ld_stage(0, 0);
    asm volatile("cp.async.commit_group;\n" ::);
    if (KT > 1) ld_stage(1, 32);
    asm volatile("cp.async.commit_group;\n" ::);
    if (KT > 2) ld_stage(2, 64);
    asm volatile("cp.async.commit_group;\n" ::);

    for (int kt = 0; kt < KT; kt++) {
        asm volatile("cp.async.wait_group 2;\n" ::);
        __syncthreads();

        if (kt + 3 < KT) ld_stage((kt + 3) & (N_STG - 1), (kt + 3) * 32);
        asm volatile("cp.async.commit_group;\n" ::);

        const __half* As = smh + (kt & (N_STG - 1)) * STGH;
        const __half* Bs = As + AH_SZ;

#pragma unroll
        for (int ks = 0; ks < 2; ks++) {
            const int kk = ks * 16;
            unsigned af[4][4];
#pragma unroll
            for (int mt = 0; mt < 4; mt++) {
                int r = wm * 64 + mt * 16 + a_r;
                ldsm_x4(af[mt][0], af[mt][1], af[mt][2], af[mt][3],
                        &As[r * AH_STR + kk + a_c]);
            }
            unsigned bf[4][2];
#pragma unroll
            for (int ntp = 0; ntp < 2; ntp++) {
                int n = wn * 32 + ntp * 16 + b_r;
                ldsm_x4(bf[ntp * 2][0], bf[ntp * 2][1], bf[ntp * 2 + 1][0], bf[ntp * 2 + 1][1],
                        &Bs[n * AH_STR + kk + b_c]);
            }
#pragma unroll
            for (int mt = 0; mt < 4; mt++)
#pragma unroll
                for (int nt = 0; nt < 4; nt++)
                    mma_f16(acc[mt][nt], af[mt], bf[nt]);
        }
    }

#pragma unroll
    for (int mt = 0; mt < 4; mt++) {
#pragma unroll
        for (int nt = 0; nt < 4; nt++) {
            int col = col0 + wn * 32 + nt * 8 + tig * 2;
            float b0 = bias[col], b1 = bias[col + 1];
#pragma unroll
            for (int half_i = 0; half_i < 2; half_i++) {
                int row = row0 + wm * 64 + mt * 16 + gid + half_i * 8;
                float v0 = acc[mt][nt][half_i * 2 + 0] + b0;
                float v1 = acc[mt][nt][half_i * 2 + 1] + b1;
                if (do_gelu) {
                    float u0 = v0, u1 = v1;
                    v0 = 0.5f * u0 * (1.0f + tanhf(0.7978845608028654f * (u0 + 0.044715f * u0 * u0 * u0)));
                    v1 = 0.5f * u1 * (1.0f + tanhf(0.7978845608028654f * (u1 + 0.044715f * u1 * u1 * u1)));
                }
                if (out_half) {
                    *reinterpret_cast<__half2*>(&((__half*)Cv)[(size_t)row * N + col]) =
                        __floats2half2_rn(v0, v1);
                } else {
                    *reinterpret_cast<float2*>(&((float*)Cv)[(size_t)row * N + col]) =
                        make_float2(v0, v1);
                }
            }
        }
    }
}

// ---------------- weight transpose + fp32->fp16 ---------------------------------
__global__ __launch_bounds__(256)
void convT_w(const float* __restrict__ W, __half* __restrict__ Wh, int K, int N)
{
    __shared__ float t[32][33];
    const int n0 = blockIdx.x * 32, k0 = blockIdx.y * 32;
    const int x = threadIdx.x, y = threadIdx.y;
#pragma unroll
    for (int i = 0; i < 32; i += 8)
        t[y + i][x] = W[(size_t)(k0 + y + i) * N + n0 + x];
    __syncthreads();
#pragma unroll
    for (int i = 0; i < 32; i += 8)
        Wh[(size_t)(n0 + y + i) * K + k0 + x] = __float2half(t[x][y + i]);
}

__global__ __launch_bounds__(256)
void conv_half(const float* __restrict__ in, __half* __restrict__ out)
{
    int i = blockIdx.x * 256 + threadIdx.x;
    float2 v = reinterpret_cast<const float2*>(in)[i];
    reinterpret_cast<__half2*>(out)[i] = __floats2half2_rn(v.x, v.y);
}

// ---------------- Flash attention, fp16 MMA, register-resident S/P --------------
// grid: (T/128, H, B), 256 threads = 8 warps; warp = 16 q rows x full 64-key tile.
// 3-stage K/V ring, prefetch distance 2 (wait_group 1).
#define AT_STR 72
#define AT_Q_SZ (128 * AT_STR)           // halves
#define AT_KV_SZ (64 * AT_STR)           // halves (per tensor)
#define AT_STG (2 * AT_KV_SZ)
#define AT_NSTG 3
#define AT_SMEM ((AT_Q_SZ + AT_NSTG * AT_STG) * 2)   // 73728 B

__global__ __launch_bounds__(256)
void attn_h(const __half* __restrict__ qkv, const int* __restrict__ lengths,
            __half* __restrict__ aout)
{
    extern __shared__ __half sa[];
    __half* Qh = sa;

    const int tid  = threadIdx.x;
    const int wid  = tid >> 5;
    const int lane = tid & 31;
    const int gid  = lane >> 2;
    const int tig  = lane & 3;

    const int b   = blockIdx.z;
    const int h   = blockIdx.y;
    const int t0  = blockIdx.x * 128;
    const int len = lengths[b];
    const size_t bt0 = (size_t)b * TT + t0;
    const size_t btb = (size_t)b * TT;
    const int qoff = h * DH;
    const int koff = DD + h * DH;
    const int voff = 2 * DD + h * DH;

    // ---- load Q tile 128x64 ----
#pragma unroll
    for (int l = 0; l < 4; l++) {
        int idx = tid + l * 256;
        int q  = idx >> 3;
        int d  = (idx & 7) * 8;
        *reinterpret_cast<float4*>(&Qh[q * AT_STR + d]) =
            *reinterpret_cast<const float4*>(&qkv[(bt0 + q) * 2304 + qoff + d]);
    }

    auto ld_kv = [&](int s, int k0) {
        __half* Kh = sa + AT_Q_SZ + s * AT_STG;
        __half* Vh = Kh + AT_KV_SZ;
#pragma unroll
        for (int l = 0; l < 2; l++) {
            int idx = tid + l * 256;
            int r  = idx >> 3;
            int d  = (idx & 7) * 8;
            unsigned dk = (unsigned)__cvta_generic_to_shared(&Kh[r * AT_STR + d]);
            unsigned dv = (unsigned)__cvta_generic_to_shared(&Vh[r * AT_STR + d]);
            const __half* sk = &qkv[(btb + k0 + r) * 2304 + koff + d];
            const __half* sv = &qkv[(btb + k0 + r) * 2304 + voff + d];
            asm volatile("cp.async.cg.shared.global [%0], [%1], 16;\n" :: "r"(dk), "l"(sk));
            asm volatile("cp.async.cg.shared.global [%0], [%1], 16;\n" :: "r"(dv), "l"(sv));
        }
    };

    const int ntiles = (len + 63) >> 6;

    ld_kv(0, 0);
    asm volatile("cp.async.commit_group;\n" ::);
    if (ntiles > 1) ld_kv(1, 64);
    asm volatile("cp.async.commit_group;\n" ::);
    __syncthreads();   // Q ready

    // ---- persistent Q fragments ----
    unsigned qf[4][4];
    {
        int r = wid * 16 + (lane & 15);
        int c = (lane >> 4) * 8;
#pragma unroll
        for (int kc = 0; kc < 4; kc++)
            ldsm_x4(qf[kc][0], qf[kc][1], qf[kc][2], qf[kc][3],
                    &Qh[r * AT_STR + kc * 16 + c]);
    }

    float o[8][4];
#pragma unroll
    for (int j = 0; j < 8; j++)
#pragma unroll
        for (int c = 0; c < 4; c++) o[j][c] = 0.f;
    float m0 = -1e30f, m1 = -1e30f, l0 = 0.f, l1 = 0.f;

    const int b_r = ((lane >> 4) & 1) * 8 + (lane & 7);
    const int b_c = ((lane >> 3) & 1) * 8;
    const int v_tI = lane >> 3;
    const int v_r  = (v_tI & 1) * 8 + (lane & 7);
    const int v_c  = (v_tI >> 1) * 8;

    int sbuf = 0;
    for (int kt = 0; kt < ntiles; kt++) {
        const int k0 = kt * 64;
        asm volatile("cp.async.wait_group 1;\n" ::);
        __syncthreads();
        if (kt + 2 < ntiles) {
            int nb = sbuf + 2; if (nb >= AT_NSTG) nb -= AT_NSTG;
            ld_kv(nb, k0 + 128);
        }
        asm volatile("cp.async.commit_group;\n" ::);

        const __half* Kh = sa + AT_Q_SZ + sbuf * AT_STG;
        const __half* Vh = Kh + AT_KV_SZ;
        if (++sbuf >= AT_NSTG) sbuf -= AT_NSTG;

        // ---- S = Q @ K^T ----
        float s[8][4];
#pragma unroll
        for (int j = 0; j < 8; j++)
#pragma unroll
            for (int c = 0; c < 4; c++) s[j][c] = 0.f;

#pragma unroll
        for (int kc = 0; kc < 4; kc++) {
            unsigned kf[8][2];
#pragma unroll
            for (int ntp = 0; ntp < 4; ntp++) {
                int n = ntp * 16 + b_r;
                ldsm_x4(kf[ntp * 2][0], kf[ntp * 2][1], kf[ntp * 2 + 1][0], kf[ntp * 2 + 1][1],
                        &Kh[n * AT_STR + kc * 16 + b_c]);
            }
#pragma unroll
            for (int j = 0; j < 8; j++)
                mma_f16(s[j], qf[kc], kf[j]);
        }

        // ---- mask + online softmax in registers ----
#pragma unroll
        for (int j = 0; j < 8; j++) {
            int kg = k0 + j * 8 + tig * 2;
            if (kg     >= len) { s[j][0] = -1e30f; s[j][2] = -1e30f; }
            if (kg + 1 >= len) { s[j][1] = -1e30f; s[j][3] = -1e30f; }
        }
        float mx0 = -1e30f, mx1 = -1e30f;
#pragma unroll
        for (int j = 0; j < 8; j++) {
            mx0 = fmaxf(mx0, fmaxf(s[j][0], s[j][1]));
            mx1 = fmaxf(mx1, fmaxf(s[j][2], s[j][3]));
        }
        mx0 = fmaxf(mx0, __shfl_xor_sync(0xffffffffu, mx0, 1));
        mx0 = fmaxf(mx0, __shfl_xor_sync(0xffffffffu, mx0, 2));
        mx1 = fmaxf(mx1, __shfl_xor_sync(0xffffffffu, mx1, 1));
        mx1 = fmaxf(mx1, __shfl_xor_sync(0xffffffffu, mx1, 2));
        float mn0 = fmaxf(m0, mx0), mn1 = fmaxf(m1, mx1);
        float sc0 = __expf(m0 - mn0), sc1 = __expf(m1 - mn1);

        float sum0 = 0.f, sum1 = 0.f;
        unsigned pf[4][4];
#pragma unroll
        for (int kc = 0; kc < 4; kc++) {
            int j0 = kc * 2, j1 = kc * 2 + 1;
            float e00 = __expf(s[j0][0] - mn0), e01 = __expf(s[j0][1] - mn0);
            float e10 = __expf(s[j0][2] - mn1), e11 = __expf(s[j0][3] - mn1);
            float f00 = __expf(s[j1][0] - mn0), f01 = __expf(s[j1][1] - mn0);
            float f10 = __expf(s[j1][2] - mn1), f11 = __expf(s[j1][3] - mn1);
            sum0 += e00 + e01 + f00 + f01;
            sum1 += e10 + e11 + f10 + f11;
            pf[kc][0] = h2pack(e00, e01);
            pf[kc][1] = h2pack(e10, e11);
            pf[kc][2] = h2pack(f00, f01);
            pf[kc][3] = h2pack(f10, f11);
        }
        sum0 += __shfl_xor_sync(0xffffffffu, sum0, 1);
        sum0 += __shfl_xor_sync(0xffffffffu, sum0, 2);
        sum1 += __shfl_xor_sync(0xffffffffu, sum1, 1);
        sum1 += __shfl_xor_sync(0xffffffffu, sum1, 2);
        l0 = l0 * sc0 + sum0;
        l1 = l1 * sc1 + sum1;
        m0 = mn0; m1 = mn1;

#pragma unroll
        for (int j = 0; j < 8; j++) {
            o[j][0] *= sc0; o[j][1] *= sc0;
            o[j][2] *= sc1; o[j][3] *= sc1;
        }

        // ---- O += P @ V ----
#pragma unroll
        for (int kc = 0; kc < 4; kc++) {
            unsigned vf[8][2];
#pragma unroll
            for (int ntp = 0; ntp < 4; ntp++) {
                ldsm_x4_t(vf[ntp * 2][0], vf[ntp * 2][1], vf[ntp * 2 + 1][0], vf[ntp * 2 + 1][1],
                          &Vh[(kc * 16 + v_r) * AT_STR + ntp * 16 + v_c]);
            }
#pragma unroll
            for (int j = 0; j < 8; j++)
                mma_f16(o[j], pf[kc], vf[j]);
        }
    }

    // ---- epilogue ----
    const int tq0 = t0 + wid * 16 + gid;
    const int tq1 = tq0 + 8;
    const float inv0 = (tq0 < len) ? (1.f / l0) : 0.f;
    const float inv1 = (tq1 < len) ? (1.f / l1) : 0.f;
#pragma unroll
    for (int j = 0; j < 8; j++) {
        int col = h * DH + j * 8 + tig * 2;
        *reinterpret_cast<__half2*>(&aout[(btb + tq0) * DD + col]) =
            __floats2half2_rn(o[j][0] * inv0, o[j][1] * inv0);
        *reinterpret_cast<__half2*>(&aout[(btb + tq1) * DD + col]) =
            __floats2half2_rn(o[j][2] * inv1, o[j][3] * inv1);
    }
}

// ---------------- residual + LayerNorm + mask (+ optional fp16 twin) ------------
__global__ __launch_bounds__(256)
void ln_kernel(const float* __restrict__ a, const float* __restrict__ r,
               const float* __restrict__ g, const float* __restrict__ beta,
               const int* __restrict__ lengths, float* __restrict__ out,
               __half* __restrict__ outh, int write_h)
{
    const int row = blockIdx.x;
    const int t = row & (TT - 1);
    const int bi = row >> 11;
    const float maskv = (t < lengths[bi]) ? 1.f : 0.f;
    const float* pa = a + (size_t)row * DD;
    const float* pr = r + (size_t)row * DD;

    float s = 0.f, s2 = 0.f;
    for (int i = threadIdx.x; i < DD; i += 256) {
        float v = pa[i] + pr[i];
        s += v; s2 += v * v;
    }
#pragma unroll
    for (int o = 16; o; o >>= 1) {
        s  += __shfl_down_sync(0xffffffffu, s,  o);
        s2 += __shfl_down_sync(0xffffffffu, s2, o);
    }
    __shared__ float ws[8], ws2[8];
    int w = threadIdx.x >> 5, lane = threadIdx.x & 31;
    if (lane == 0) { ws[w] = s; ws2[w] = s2; }
    __syncthreads();
    if (threadIdx.x == 0) {
        float S = 0.f, S2 = 0.f;
        for (int i = 0; i < 8; i++) { S += ws[i]; S2 += ws2[i]; }
        ws[0] = S; ws2[0] = S2;
    }
    __syncthreads();
    const float mu = ws[0] * (1.f / DD);
    const float var = ws2[0] * (1.f / DD) - mu * mu;
    const float rstd = rsqrtf(var + 1e-5f);
    for (int i = threadIdx.x; i < DD; i += 256) {
        float v = pa[i] + pr[i];
        float y = ((v - mu) * rstd * g[i] + beta[i]) * maskv;
        out[(size_t)row * DD + i] = y;
        if (write_h) outh[(size_t)row * DD + i] = __float2half(y);
    }
}

// ---------------- launcher ------------------------------------------------------
extern "C" void kernel_launch(void* const* d_in, const int* in_sizes, int n_in,
                              void* d_out, int out_size)
{
    const float* x      = (const float*)d_in[0];
    const int*   lens   = (const int*)  d_in[1];
    const float* w_qkv  = (const float*)d_in[2];
    const float* b_qkv  = (const float*)d_in[3];
    const float* w_proj = (const float*)d_in[4];
    const float* b_proj = (const float*)d_in[5];
    const float* ln1_g  = (const float*)d_in[6];
    const float* ln1_b  = (const float*)d_in[7];
    const float* w_fc   = (const float*)d_in[8];
    const float* b_fc   = (const float*)d_in[9];
    const float* w_out  = (const float*)d_in[10];
    const float* b_out  = (const float*)d_in[11];
    const float* ln2_g  = (const float*)d_in[12];
    const float* ln2_b  = (const float*)d_in[13];
    float* out = (float*)d_out;

    float  *p_proj, *p_n, *p_m;
    __half *p_xh, *p_qkvh, *p_attnh, *p_nh, *p_h1h;
    __half *p_wqkvTh, *p_wprojTh, *p_wfcTh, *p_woutTh;
    cudaGetSymbolAddress((void**)&p_proj, g_proj);
    cudaGetSymbolAddress((void**)&p_n,    g_n);
    cudaGetSymbolAddress((void**)&p_m,    g_m);
    cudaGetSymbolAddress((void**)&p_xh,    g_xh);
    cudaGetSymbolAddress((void**)&p_qkvh,  g_qkvh);
    cudaGetSymbolAddress((void**)&p_attnh, g_attnh);
    cudaGetSymbolAddress((void**)&p_nh,    g_nh);
    cudaGetSymbolAddress((void**)&p_h1h,   g_h1h);
    cudaGetSymbolAddress((void**)&p_wqkvTh,  g_wqkvTh);
    cudaGetSymbolAddress((void**)&p_wprojTh, g_wprojTh);
    cudaGetSymbolAddress((void**)&p_wfcTh,   g_wfcTh);
    cudaGetSymbolAddress((void**)&p_woutTh,  g_woutTh);

    cudaFuncSetAttribute(gemm_h, cudaFuncAttributeMaxDynamicSharedMemorySize, GEMMH_SMEM);
    cudaFuncSetAttribute(attn_h, cudaFuncAttributeMaxDynamicSharedMemorySize, AT_SMEM);

    // 0) weight transpose+convert, x convert
    convT_w<<<dim3(2304 / 32, 768 / 32),  dim3(32, 8)>>>(w_qkv,  p_wqkvTh,  768, 2304);
    convT_w<<<dim3(768 / 32,  768 / 32),  dim3(32, 8)>>>(w_proj, p_wprojTh, 768, 768);
    convT_w<<<dim3(3072 / 32, 768 / 32),  dim3(32, 8)>>>(w_fc,   p_wfcTh,   768, 3072);
    convT_w<<<dim3(768 / 32,  3072 / 32), dim3(32, 8)>>>(w_out,  p_woutTh,  3072, 768);
    conv_half<<<(BT * DD / 2) / 256, 256>>>(x, p_xh);

    // 1) qkv = x @ w_qkv + b_qkv                [4096, 2304] fp16
    gemm_h<<<dim3(2304 / 128, BT / 128), 256, GEMMH_SMEM>>>(p_xh, p_wqkvTh, b_qkv, p_qkvh, BT, 2304, DD, 0, 1);

    // 2) attention (fp16 MMA, register softmax)  [4096, 768] fp16
    attn_h<<<dim3(TT / 128, HH, BB), 256, AT_SMEM>>>(p_qkvh, lens, p_attnh);

    // 3) proj = attn @ w_proj + b_proj          [4096, 768] fp32
    gemm_h<<<dim3(DD / 128, BT / 128), 256, GEMMH_SMEM>>>(p_attnh, p_wprojTh, b_proj, p_proj, BT, DD, DD, 0, 0);

    // 4) n = LN(x + proj) * mask  (+ fp16 twin)
    ln_kernel<<<BT, 256>>>(x, p_proj, ln1_g, ln1_b, lens, p_n, p_nh, 1);

    // 5) h1 = gelu(n @ w_fc + b_fc)             [4096, 3072] fp16
    gemm_h<<<dim3(3072 / 128, BT / 128), 256, GEMMH_SMEM>>>(p_nh, p_wfcTh, b_fc, p_h1h, BT, 3072, DD, 1, 1);

    // 6) m = h1 @ w_out + b_out                 [4096, 768] fp32
    gemm_h<<<dim3(DD / 128, BT / 128), 256, GEMMH_SMEM>>>(p_h1h, p_woutTh, b_out, p_m, BT, DD, 3072, 0, 0);

    // 7) out = LN(n + m) * mask
    ln_kernel<<<BT, 256>>>(p_n, p_m, ln2_g, ln2_b, lens, out, p_nh, 0);
}

// round 12
// speedup vs baseline: 1.0485x; 1.0485x over previous
#include <cuda_runtime.h>
#include <cuda_fp16.h>
#include <cstdint>

#define BB 2
#define TT 2048
#define DD 768
#define HH 12
#define DH 64
#define BT (BB*TT)

// ---------------- scratch (static device arrays; zero-initialized) --------------
__device__ float  g_proj[(size_t)BT * DD];
__device__ float  g_n   [(size_t)BT * DD];
__device__ float  g_m   [(size_t)BT * DD];
__device__ __half g_xh   [(size_t)BT * DD];
__device__ __half g_qkvh [(size_t)BT * 2304];
__device__ __half g_attnh[(size_t)BT * DD];
__device__ __half g_nh   [(size_t)BT * DD];
__device__ __half g_h1h  [(size_t)BT * 3072];
// fp16 weights, natural [K][N] layout
__device__ __half g_wqkvh [(size_t)768 * 2304];
__device__ __half g_wprojh[(size_t)768 * 768];
__device__ __half g_wfch  [(size_t)768 * 3072];
__device__ __half g_wouth [(size_t)3072 * 768];

__device__ __forceinline__ void mma_f16(float* c, const unsigned* a, const unsigned* b) {
    asm volatile(
        "mma.sync.aligned.m16n8k16.row.col.f32.f16.f16.f32 "
        "{%0,%1,%2,%3}, {%4,%5,%6,%7}, {%8,%9}, {%0,%1,%2,%3};"
        : "+f"(c[0]), "+f"(c[1]), "+f"(c[2]), "+f"(c[3])
        : "r"(a[0]), "r"(a[1]), "r"(a[2]), "r"(a[3]), "r"(b[0]), "r"(b[1]));
}

__device__ __forceinline__ void ldsm_x4(unsigned& r0, unsigned& r1, unsigned& r2, unsigned& r3,
                                        const __half* p) {
    unsigned addr = (unsigned)__cvta_generic_to_shared(p);
    asm volatile("ldmatrix.sync.aligned.m8n8.x4.shared.b16 {%0,%1,%2,%3}, [%4];"
                 : "=r"(r0), "=r"(r1), "=r"(r2), "=r"(r3) : "r"(addr));
}

__device__ __forceinline__ void ldsm_x4_t(unsigned& r0, unsigned& r1, unsigned& r2, unsigned& r3,
                                          const __half* p) {
    unsigned addr = (unsigned)__cvta_generic_to_shared(p);
    asm volatile("ldmatrix.sync.aligned.m8n8.x4.trans.shared.b16 {%0,%1,%2,%3}, [%4];"
                 : "=r"(r0), "=r"(r1), "=r"(r2), "=r"(r3) : "r"(addr));
}

__device__ __forceinline__ unsigned h2pack(float a, float b) {
    __half2 h = __floats2half2_rn(a, b);
    return *reinterpret_cast<unsigned*>(&h);
}

// ---------------- fp16 tensor-core GEMM ------------------------------------------
// C[M,N] = Ah[M,K] @ Wh[K,N] + bias. A [m][k] smem + ldsm; B [k][n] smem + ldsm.trans.
// BM=128 BN=128 BK=32, 256 threads = 8 warps (2x4), warp tile 64x32.
// Ragged early-exit: row-tiles with (row % TT) >= lengths[row/TT] are skipped.
#define AH_STR 40
#define AH_SZ (128 * AH_STR)            // halves
#define BH_STR 136
#define BH_SZ (32 * BH_STR)             // halves
#define STGH (AH_SZ + BH_SZ)
#define N_STG 3
#define GEMMH_SMEM (N_STG * STGH * 2)   // 56832 B

__global__ __launch_bounds__(256)
void gemm_h(const __half* __restrict__ Ah, const __half* __restrict__ Wh,
            const float* __restrict__ bias, void* __restrict__ Cv,
            const int* __restrict__ lengths,
            int M, int N, int K, int do_gelu, int out_half)
{
    extern __shared__ __half smh[];

    const int row0 = blockIdx.y * 128;
    if ((row0 & (TT - 1)) >= lengths[row0 >> 11]) return;   // ragged skip

    const int tid  = threadIdx.x;
    const int wid  = tid >> 5;
    const int lane = tid & 31;
    const int gid  = lane >> 2;
    const int tig  = lane & 3;
    const int wm   = wid >> 2;
    const int wn   = wid & 3;
    const int col0 = blockIdx.x * 128;

    const int a_r  = (lane & 15);
    const int a_c  = (lane >> 4) * 8;
    const int tI   = lane >> 3;                    // trans-frag tile id
    const int bt_r = (tI & 1) * 8 + (lane & 7);    // k-row within 16
    const int bt_c = (tI >> 1) * 8;                // n-col within 16

    float acc[4][4][4];
#pragma unroll
    for (int mt = 0; mt < 4; mt++)
#pragma unroll
        for (int nt = 0; nt < 4; nt++)
#pragma unroll
            for (int c = 0; c < 4; c++) acc[mt][nt][c] = 0.f;

    const int KT = K >> 5;

    auto ld_stage = [&](int s, int k0) {
        __half* As = smh + s * STGH;
        __half* Bs = As + AH_SZ;
        // A: 128x32, 512 16B chunks
#pragma unroll
        for (int l = 0; l < 2; l++) {
            int ci = tid + l * 256;
            int r  = ci >> 2;
            int cc = (ci & 3) * 8;
            unsigned dst = (unsigned)__cvta_generic_to_shared(&As[r * AH_STR + cc]);
            const __half* src = &Ah[(size_t)(row0 + r) * K + k0 + cc];
            asm volatile("cp.async.cg.shared.global [%0], [%1], 16;\n" :: "r"(dst), "l"(src));
        }
        // B: 32x128 from W[k][n], 512 16B chunks (coalesced along N)
#pragma unroll
        for (int l = 0; l < 2; l++) {
            int ci = tid + l * 256;
            int r  = ci >> 4;                // 0..31 (k)
            int cc = (ci & 15) * 8;          // 0..120 (n)
            unsigned dst = (unsigned)__cvta_generic_to_shared(&Bs[r * BH_STR + cc]);
            const __half* src = &Wh[(size_t)(k0 + r) * N + col0 + cc];
            asm volatile("cp.async.cg.shared.global [%0], [%1], 16;\n" :: "r"(dst), "l"(src));
        }
    };

    ld_stage(0, 0);
    asm volatile("cp.async.commit_group;\n" ::);
    if (KT > 1) ld_stage(1, 32);
    asm volatile("cp.async.commit_group;\n" ::);

    int buf = 0;
    for (int kt = 0; kt < KT; kt++) {
        asm volatile("cp.async.wait_group 1;\n" ::);
        __syncthreads();

        if (kt + 2 < KT) {
            int nb = buf + 2; if (nb >= N_STG) nb -= N_STG;
            ld_stage(nb, (kt + 2) * 32);
        }
        asm volatile("cp.async.commit_group;\n" ::);

        const __half* As = smh + buf * STGH;
        const __half* Bs = As + AH_SZ;

#pragma unroll
        for (int ks = 0; ks < 2; ks++) {
            const int kk = ks * 16;
            unsigned af[4][4];
#pragma unroll
            for (int mt = 0; mt < 4; mt++) {
                int r = wm * 64 + mt * 16 + a_r;
                ldsm_x4(af[mt][0], af[mt][1], af[mt][2], af[mt][3],
                        &As[r * AH_STR + kk + a_c]);
            }
            unsigned bf[4][2];
#pragma unroll
            for (int ntp = 0; ntp < 2; ntp++) {
                ldsm_x4_t(bf[ntp * 2][0], bf[ntp * 2][1], bf[ntp * 2 + 1][0], bf[ntp * 2 + 1][1],
                          &Bs[(kk + bt_r) * BH_STR + wn * 32 + ntp * 16 + bt_c]);
            }
#pragma unroll
            for (int mt = 0; mt < 4; mt++)
#pragma unroll
                for (int nt = 0; nt < 4; nt++)
                    mma_f16(acc[mt][nt], af[mt], bf[nt]);
        }
        if (++buf >= N_STG) buf -= N_STG;
    }

#pragma unroll
    for (int mt = 0; mt < 4; mt++) {
#pragma unroll
        for (int nt = 0; nt < 4; nt++) {
            int col = col0 + wn * 32 + nt * 8 + tig * 2;
            float b0 = bias[col], b1 = bias[col + 1];
#pragma unroll
            for (int half_i = 0; half_i < 2; half_i++) {
                int row = row0 + wm * 64 + mt * 16 + gid + half_i * 8;
                float v0 = acc[mt][nt][half_i * 2 + 0] + b0;
                float v1 = acc[mt][nt][half_i * 2 + 1] + b1;
                if (do_gelu) {
                    float u0 = v0, u1 = v1;
                    v0 = 0.5f * u0 * (1.0f + tanhf(0.7978845608028654f * (u0 + 0.044715f * u0 * u0 * u0)));
                    v1 = 0.5f * u1 * (1.0f + tanhf(0.7978845608028654f * (u1 + 0.044715f * u1 * u1 * u1)));
                }
                if (out_half) {
                    *reinterpret_cast<__half2*>(&((__half*)Cv)[(size_t)row * N + col]) =
                        __floats2half2_rn(v0, v1);
                } else {
                    *reinterpret_cast<float2*>(&((float*)Cv)[(size_t)row * N + col]) =
                        make_float2(v0, v1);
                }
            }
        }
    }
}

// ---------------- elementwise fp32 -> fp16 ---------------------------------------
__global__ __launch_bounds__(256)
void conv_half(const float* __restrict__ in, __half* __restrict__ out)
{
    int i = blockIdx.x * 256 + threadIdx.x;
    float2 v = reinterpret_cast<const float2*>(in)[i];
    reinterpret_cast<__half2*>(out)[i] = __floats2half2_rn(v.x, v.y);
}

// ---------------- Flash attention, fp16 MMA, register-resident S/P --------------
#define AT_STR 72
#define AT_Q_SZ (128 * AT_STR)
#define AT_KV_SZ (64 * AT_STR)
#define AT_STG (2 * AT_KV_SZ)
#define AT_NSTG 3
#define AT_SMEM ((AT_Q_SZ + AT_NSTG * AT_STG) * 2)   // 73728 B

__global__ __launch_bounds__(256)
void attn_h(const __half* __restrict__ qkv, const int* __restrict__ lengths,
            __half* __restrict__ aout)
{
    extern __shared__ __half sa[];
    __half* Qh = sa;

    const int b   = blockIdx.z;
    const int t0  = blockIdx.x * 128;
    const int len = lengths[b];
    if (t0 >= len) return;              // ragged skip (outputs stay zero-init)

    const int tid  = threadIdx.x;
    const int wid  = tid >> 5;
    const int lane = tid & 31;
    const int gid  = lane >> 2;
    const int tig  = lane & 3;
    const int h    = blockIdx.y;
    const size_t bt0 = (size_t)b * TT + t0;
    const size_t btb = (size_t)b * TT;
    const int qoff = h * DH;
    const int koff = DD + h * DH;
    const int voff = 2 * DD + h * DH;

#pragma unroll
    for (int l = 0; l < 4; l++) {
        int idx = tid + l * 256;
        int q  = idx >> 3;
        int d  = (idx & 7) * 8;
        *reinterpret_cast<float4*>(&Qh[q * AT_STR + d]) =
            *reinterpret_cast<const float4*>(&qkv[(bt0 + q) * 2304 + qoff + d]);
    }

    auto ld_kv = [&](int s, int k0) {
        __half* Kh = sa + AT_Q_SZ + s * AT_STG;
        __half* Vh = Kh + AT_KV_SZ;
#pragma unroll
        for (int l = 0; l < 2; l++) {
            int idx = tid + l * 256;
            int r  = idx >> 3;
            int d  = (idx & 7) * 8;
            unsigned dk = (unsigned)__cvta_generic_to_shared(&Kh[r * AT_STR + d]);
            unsigned dv = (unsigned)__cvta_generic_to_shared(&Vh[r * AT_STR + d]);
            const __half* sk = &qkv[(btb + k0 + r) * 2304 + koff + d];
            const __half* sv = &qkv[(btb + k0 + r) * 2304 + voff + d];
            asm volatile("cp.async.cg.shared.global [%0], [%1], 16;\n" :: "r"(dk), "l"(sk));
            asm volatile("cp.async.cg.shared.global [%0], [%1], 16;\n" :: "r"(dv), "l"(sv));
        }
    };

    const int ntiles = (len + 63) >> 6;

    ld_kv(0, 0);
    asm volatile("cp.async.commit_group;\n" ::);
    if (ntiles > 1) ld_kv(1, 64);
    asm volatile("cp.async.commit_group;\n" ::);
    __syncthreads();

    unsigned qf[4][4];
    {
        int r = wid * 16 + (lane & 15);
        int c = (lane >> 4) * 8;
#pragma unroll
        for (int kc = 0; kc < 4; kc++)
            ldsm_x4(qf[kc][0], qf[kc][1], qf[kc][2], qf[kc][3],
                    &Qh[r * AT_STR + kc * 16 + c]);
    }

    float o[8][4];
#pragma unroll
    for (int j = 0; j < 8; j++)
#pragma unroll
        for (int c = 0; c < 4; c++) o[j][c] = 0.f;
    float m0 = -1e30f, m1 = -1e30f, l0 = 0.f, l1 = 0.f;

    const int b_r = ((lane >> 4) & 1) * 8 + (lane & 7);
    const int b_c = ((lane >> 3) & 1) * 8;
    const int v_tI = lane >> 3;
    const int v_r  = (v_tI & 1) * 8 + (lane & 7);
    const int v_c  = (v_tI >> 1) * 8;

    int sbuf = 0;
    for (int kt = 0; kt < ntiles; kt++) {
        const int k0 = kt * 64;
        asm volatile("cp.async.wait_group 1;\n" ::);
        __syncthreads();
        if (kt + 2 < ntiles) {
            int nb = sbuf + 2; if (nb >= AT_NSTG) nb -= AT_NSTG;
            ld_kv(nb, k0 + 128);
        }
        asm volatile("cp.async.commit_group;\n" ::);

        const __half* Kh = sa + AT_Q_SZ + sbuf * AT_STG;
        const __half* Vh = Kh + AT_KV_SZ;
        if (++sbuf >= AT_NSTG) sbuf -= AT_NSTG;

        float s[8][4];
#pragma unroll
        for (int j = 0; j < 8; j++)
#pragma unroll
            for (int c = 0; c < 4; c++) s[j][c] = 0.f;

#pragma unroll
        for (int kc = 0; kc < 4; kc++) {
            unsigned kf[8][2];
#pragma unroll
            for (int ntp = 0; ntp < 4; ntp++) {
                int n = ntp * 16 + b_r;
                ldsm_x4(kf[ntp * 2][0], kf[ntp * 2][1], kf[ntp * 2 + 1][0], kf[ntp * 2 + 1][1],
                        &Kh[n * AT_STR + kc * 16 + b_c]);
            }
#pragma unroll
            for (int j = 0; j < 8; j++)
                mma_f16(s[j], qf[kc], kf[j]);
        }

#pragma unroll
        for (int j = 0; j < 8; j++) {
            int kg = k0 + j * 8 + tig * 2;
            if (kg     >= len) { s[j][0] = -1e30f; s[j][2] = -1e30f; }
            if (kg + 1 >= len) { s[j][1] = -1e30f; s[j][3] = -1e30f; }
        }
        float mx0 = -1e30f, mx1 = -1e30f;
#pragma unroll
        for (int j = 0; j < 8; j++) {
            mx0 = fmaxf(mx0, fmaxf(s[j][0], s[j][1]));
            mx1 = fmaxf(mx1, fmaxf(s[j][2], s[j][3]));
        }
        mx0 = fmaxf(mx0, __shfl_xor_sync(0xffffffffu, mx0, 1));
        mx0 = fmaxf(mx0, __shfl_xor_sync(0xffffffffu, mx0, 2));
        mx1 = fmaxf(mx1, __shfl_xor_sync(0xffffffffu, mx1, 1));
        mx1 = fmaxf(mx1, __shfl_xor_sync(0xffffffffu, mx1, 2));
        float mn0 = fmaxf(m0, mx0), mn1 = fmaxf(m1, mx1);
        float sc0 = __expf(m0 - mn0), sc1 = __expf(m1 - mn1);

        float sum0 = 0.f, sum1 = 0.f;
        unsigned pf[4][4];
#pragma unroll
        for (int kc = 0; kc < 4; kc++) {
            int j0 = kc * 2, j1 = kc * 2 + 1;
            float e00 = __expf(s[j0][0] - mn0), e01 = __expf(s[j0][1] - mn0);
            float e10 = __expf(s[j0][2] - mn1), e11 = __expf(s[j0][3] - mn1);
            float f00 = __expf(s[j1][0] - mn0), f01 = __expf(s[j1][1] - mn0);
            float f10 = __expf(s[j1][2] - mn1), f11 = __expf(s[j1][3] - mn1);
            sum0 += e00 + e01 + f00 + f01;
            sum1 += e10 + e11 + f10 + f11;
            pf[kc][0] = h2pack(e00, e01);
            pf[kc][1] = h2pack(e10, e11);
            pf[kc][2] = h2pack(f00, f01);
            pf[kc][3] = h2pack(f10, f11);
        }
        sum0 += __shfl_xor_sync(0xffffffffu, sum0, 1);
        sum0 += __shfl_xor_sync(0xffffffffu, sum0, 2);
        sum1 += __shfl_xor_sync(0xffffffffu, sum1, 1);
        sum1 += __shfl_xor_sync(0xffffffffu, sum1, 2);
        l0 = l0 * sc0 + sum0;
        l1 = l1 * sc1 + sum1;
        m0 = mn0; m1 = mn1;

#pragma unroll
        for (int j = 0; j < 8; j++) {
            o[j][0] *= sc0; o[j][1] *= sc0;
            o[j][2] *= sc1; o[j][3] *= sc1;
        }

#pragma unroll
        for (int kc = 0; kc < 4; kc++) {
            unsigned vf[8][2];
#pragma unroll
            for (int ntp = 0; ntp < 4; ntp++) {
                ldsm_x4_t(vf[ntp * 2][0], vf[ntp * 2][1], vf[ntp * 2 + 1][0], vf[ntp * 2 + 1][1],
                          &Vh[(kc * 16 + v_r) * AT_STR + ntp * 16 + v_c]);
            }
#pragma unroll
            for (int j = 0; j < 8; j++)
                mma_f16(o[j], pf[kc], vf[j]);
        }
    }

    const int tq0 = t0 + wid * 16 + gid;
    const int tq1 = tq0 + 8;
    const float inv0 = (tq0 < len) ? (1.f / l0) : 0.f;
    const float inv1 = (tq1 < len) ? (1.f / l1) : 0.f;
#pragma unroll
    for (int j = 0; j < 8; j++) {
        int col = h * DH + j * 8 + tig * 2;
        *reinterpret_cast<__half2*>(&aout[(btb + tq0) * DD + col]) =
            __floats2half2_rn(o[j][0] * inv0, o[j][1] * inv0);
        *reinterpret_cast<__half2*>(&aout[(btb + tq1) * DD + col]) =
            __floats2half2_rn(o[j][2] * inv1, o[j][3] * inv1);
    }
}

// ---------------- residual + LayerNorm + mask (+ optional fp16 twin) ------------
__global__ __launch_bounds__(256)
void ln_kernel(const float* __restrict__ a, const float* __restrict__ r,
               const float* __restrict__ g, const float* __restrict__ beta,
               const int* __restrict__ lengths, float* __restrict__ out,
               __half* __restrict__ outh, int write_h)
{
    const int row = blockIdx.x;
    const int t = row & (TT - 1);
    const int bi = row >> 11;
    const float maskv = (t < lengths[bi]) ? 1.f : 0.f;
    const float* pa = a + (size_t)row * DD;
    const float* pr = r + (size_t)row * DD;

    float s = 0.f, s2 = 0.f;
    for (int i = threadIdx.x; i < DD; i += 256) {
        float v = pa[i] + pr[i];
        s += v; s2 += v * v;
    }
#pragma unroll
    for (int o = 16; o; o >>= 1) {
        s  += __shfl_down_sync(0xffffffffu, s,  o);
        s2 += __shfl_down_sync(0xffffffffu, s2, o);
    }
    __shared__ float ws[8], ws2[8];
    int w = threadIdx.x >> 5, lane = threadIdx.x & 31;
    if (lane == 0) { ws[w] = s; ws2[w] = s2; }
    __syncthreads();
    if (threadIdx.x == 0) {
        float S = 0.f, S2 = 0.f;
        for (int i = 0; i < 8; i++) { S += ws[i]; S2 += ws2[i]; }
        ws[0] = S; ws2[0] = S2;
    }
    __syncthreads();
    const float mu = ws[0] * (1.f / DD);
    const float var = ws2[0] * (1.f / DD) - mu * mu;
    const float rstd = rsqrtf(var + 1e-5f);
    for (int i = threadIdx.x; i < DD; i += 256) {
        float v = pa[i] + pr[i];
        float y = ((v - mu) * rstd * g[i] + beta[i]) * maskv;
        out[(size_t)row * DD + i] = y;
        if (write_h) outh[(size_t)row * DD + i] = __float2half(y);
    }
}

// ---------------- launcher ------------------------------------------------------
extern "C" void kernel_launch(void* const* d_in, const int* in_sizes, int n_in,
                              void* d_out, int out_size)
{
    const float* x      = (const float*)d_in[0];
    const int*   lens   = (const int*)  d_in[1];
    const float* w_qkv  = (const float*)d_in[2];
    const float* b_qkv  = (const float*)d_in[3];
    const float* w_proj = (const float*)d_in[4];
    const float* b_proj = (const float*)d_in[5];
    const float* ln1_g  = (const float*)d_in[6];
    const float* ln1_b  = (const float*)d_in[7];
    const float* w_fc   = (const float*)d_in[8];
    const float* b_fc   = (const float*)d_in[9];
    const float* w_out  = (const float*)d_in[10];
    const float* b_out  = (const float*)d_in[11];
    const float* ln2_g  = (const float*)d_in[12];
    const float* ln2_b  = (const float*)d_in[13];
    float* out = (float*)d_out;

    float  *p_proj, *p_n, *p_m;
    __half *p_xh, *p_qkvh, *p_attnh, *p_nh, *p_h1h;
    __half *p_wqkvh, *p_wprojh, *p_wfch, *p_wouth;
    cudaGetSymbolAddress((void**)&p_proj, g_proj);
    cudaGetSymbolAddress((void**)&p_n,    g_n);
    cudaGetSymbolAddress((void**)&p_m,    g_m);
    cudaGetSymbolAddress((void**)&p_xh,    g_xh);
    cudaGetSymbolAddress((void**)&p_qkvh,  g_qkvh);
    cudaGetSymbolAddress((void**)&p_attnh, g_attnh);
    cudaGetSymbolAddress((void**)&p_nh,    g_nh);
    cudaGetSymbolAddress((void**)&p_h1h,   g_h1h);
    cudaGetSymbolAddress((void**)&p_wqkvh,  g_wqkvh);
    cudaGetSymbolAddress((void**)&p_wprojh, g_wprojh);
    cudaGetSymbolAddress((void**)&p_wfch,   g_wfch);
    cudaGetSymbolAddress((void**)&p_wouth,  g_wouth);

    cudaFuncSetAttribute(gemm_h, cudaFuncAttributeMaxDynamicSharedMemorySize, GEMMH_SMEM);
    cudaFuncSetAttribute(attn_h, cudaFuncAttributeMaxDynamicSharedMemorySize, AT_SMEM);

    // 0) elementwise fp32->fp16 converts (weights keep [K][N] layout)
    conv_half<<<(768 * 2304 / 2) / 256, 256>>>(w_qkv,  p_wqkvh);
    conv_half<<<(768 * 768  / 2) / 256, 256>>>(w_proj, p_wprojh);
    conv_half<<<(768 * 3072 / 2) / 256, 256>>>(w_fc,   p_wfch);
    conv_half<<<(3072 * 768 / 2) / 256, 256>>>(w_out,  p_wouth);
    conv_half<<<(BT * DD / 2) / 256, 256>>>(x, p_xh);

    // 1) qkv = x @ w_qkv + b_qkv                [4096, 2304] fp16
    gemm_h<<<dim3(2304 / 128, BT / 128), 256, GEMMH_SMEM>>>(p_xh, p_wqkvh, b_qkv, p_qkvh, lens, BT, 2304, DD, 0, 1);

    // 2) attention (fp16 MMA, register softmax)  [4096, 768] fp16
    attn_h<<<dim3(TT / 128, HH, BB), 256, AT_SMEM>>>(p_qkvh, lens, p_attnh);

    // 3) proj = attn @ w_proj + b_proj          [4096, 768] fp32
    gemm_h<<<dim3(DD / 128, BT / 128), 256, GEMMH_SMEM>>>(p_attnh, p_wprojh, b_proj, p_proj, lens, BT, DD, DD, 0, 0);

    // 4) n = LN(x + proj) * mask  (+ fp16 twin)
    ln_kernel<<<BT, 256>>>(x, p_proj, ln1_g, ln1_b, lens, p_n, p_nh, 1);

    // 5) h1 = gelu(n @ w_fc + b_fc)             [4096, 3072] fp16
    gemm_h<<<dim3(3072 / 128, BT / 128), 256, GEMMH_SMEM>>>(p_nh, p_wfch, b_fc, p_h1h, lens, BT, 3072, DD, 1, 1);

    // 6) m = h1 @ w_out + b_out                 [4096, 768] fp32
    gemm_h<<<dim3(DD / 128, BT / 128), 256, GEMMH_SMEM>>>(p_h1h, p_wouth, b_out, p_m, lens, BT, DD, 3072, 0, 0);

    // 7) out = LN(n + m) * mask
    ln_kernel<<<BT, 256>>>(p_n, p_m, ln2_g, ln2_b, lens, out, p_nh, 0);
}

// round 13
// speedup vs baseline: 1.1206x; 1.0688x over previous
#include <cuda_runtime.h>
#include <cuda_fp16.h>
#include <cstdint>

#define BB 2
#define TT 2048
#define DD 768
#define HH 12
#define DH 64
#define BT (BB*TT)

// ---------------- scratch (static device arrays; zero-initialized) --------------
__device__ float  g_proj[(size_t)BT * DD];
__device__ float  g_n   [(size_t)BT * DD];
__device__ float  g_m   [(size_t)BT * DD];
__device__ __half g_xh   [(size_t)BT * DD];
__device__ __half g_qkvh [(size_t)BT * 2304];
__device__ __half g_attnh[(size_t)BT * DD];
__device__ __half g_nh   [(size_t)BT * DD];
__device__ __half g_h1h  [(size_t)BT * 3072];
// fp16 weights, natural [K][N] layout
__device__ __half g_wqkvh [(size_t)768 * 2304];
__device__ __half g_wprojh[(size_t)768 * 768];
__device__ __half g_wfch  [(size_t)768 * 3072];
__device__ __half g_wouth [(size_t)3072 * 768];

__device__ __forceinline__ void mma_f16(float* c, const unsigned* a, const unsigned* b) {
    asm volatile(
        "mma.sync.aligned.m16n8k16.row.col.f32.f16.f16.f32 "
        "{%0,%1,%2,%3}, {%4,%5,%6,%7}, {%8,%9}, {%0,%1,%2,%3};"
        : "+f"(c[0]), "+f"(c[1]), "+f"(c[2]), "+f"(c[3])
        : "r"(a[0]), "r"(a[1]), "r"(a[2]), "r"(a[3]), "r"(b[0]), "r"(b[1]));
}

__device__ __forceinline__ void ldsm_x4(unsigned& r0, unsigned& r1, unsigned& r2, unsigned& r3,
                                        const __half* p) {
    unsigned addr = (unsigned)__cvta_generic_to_shared(p);
    asm volatile("ldmatrix.sync.aligned.m8n8.x4.shared.b16 {%0,%1,%2,%3}, [%4];"
                 : "=r"(r0), "=r"(r1), "=r"(r2), "=r"(r3) : "r"(addr));
}

__device__ __forceinline__ void ldsm_x4_t(unsigned& r0, unsigned& r1, unsigned& r2, unsigned& r3,
                                          const __half* p) {
    unsigned addr = (unsigned)__cvta_generic_to_shared(p);
    asm volatile("ldmatrix.sync.aligned.m8n8.x4.trans.shared.b16 {%0,%1,%2,%3}, [%4];"
                 : "=r"(r0), "=r"(r1), "=r"(r2), "=r"(r3) : "r"(addr));
}

__device__ __forceinline__ unsigned h2pack(float a, float b) {
    __half2 h = __floats2half2_rn(a, b);
    return *reinterpret_cast<unsigned*>(&h);
}

// ---------------- fp16 tensor-core GEMM, BK=64, 3-stage cp.async ---------------
// C[M,N] = Ah[M,K] @ Wh[K,N] + bias. A [m][k] + ldsm; B [k][n] + ldsm.trans.
// BM=128 BN=128 BK=64, 256 threads = 8 warps (2x4), warp tile 64x32.
// Ragged early-exit on row-tiles past lengths.
#define A_STR 72                        // halves; 144B rows, ldsm conflict-free
#define A_SZH (128 * A_STR)             // 9216 halves
#define B_STR 136                       // halves; 272B rows, conflict-free
#define B_SZH (64 * B_STR)              // 8704 halves
#define STGH (A_SZH + B_SZH)            // 17920 halves
#define N_STG 3
#define GEMMH_SMEM (N_STG * STGH * 2)   // 107520 B

__global__ __launch_bounds__(256)
void gemm_h(const __half* __restrict__ Ah, const __half* __restrict__ Wh,
            const float* __restrict__ bias, void* __restrict__ Cv,
            const int* __restrict__ lengths,
            int M, int N, int K, int do_gelu, int out_half)
{
    extern __shared__ __half smh[];

    const int row0 = blockIdx.y * 128;
    if ((row0 & (TT - 1)) >= lengths[row0 >> 11]) return;   // ragged skip

    const int tid  = threadIdx.x;
    const int wid  = tid >> 5;
    const int lane = tid & 31;
    const int gid  = lane >> 2;
    const int tig  = lane & 3;
    const int wm   = wid >> 2;
    const int wn   = wid & 3;
    const int col0 = blockIdx.x * 128;

    const int a_r  = (lane & 15);
    const int a_c  = (lane >> 4) * 8;
    const int tI   = lane >> 3;
    const int bt_r = (tI & 1) * 8 + (lane & 7);
    const int bt_c = (tI >> 1) * 8;

    float acc[4][4][4];
#pragma unroll
    for (int mt = 0; mt < 4; mt++)
#pragma unroll
        for (int nt = 0; nt < 4; nt++)
#pragma unroll
            for (int c = 0; c < 4; c++) acc[mt][nt][c] = 0.f;

    const int KT = K >> 6;

    auto ld_stage = [&](int s, int k0) {
        __half* As = smh + s * STGH;
        __half* Bs = As + A_SZH;
        // A: 128x64 halves = 1024 16B chunks, 4/thread
#pragma unroll
        for (int l = 0; l < 4; l++) {
            int ci = tid + l * 256;
            int r  = ci >> 3;                // 0..127
            int cc = (ci & 7) * 8;           // 0..56
            unsigned dst = (unsigned)__cvta_generic_to_shared(&As[r * A_STR + cc]);
            const __half* src = &Ah[(size_t)(row0 + r) * K + k0 + cc];
            asm volatile("cp.async.cg.shared.global [%0], [%1], 16;\n" :: "r"(dst), "l"(src));
        }
        // B: 64x128 halves from W[k][n] = 1024 16B chunks, 4/thread
#pragma unroll
        for (int l = 0; l < 4; l++) {
            int ci = tid + l * 256;
            int r  = ci >> 4;                // 0..63 (k)
            int cc = (ci & 15) * 8;          // 0..120 (n)
            unsigned dst = (unsigned)__cvta_generic_to_shared(&Bs[r * B_STR + cc]);
            const __half* src = &Wh[(size_t)(k0 + r) * N + col0 + cc];
            asm volatile("cp.async.cg.shared.global [%0], [%1], 16;\n" :: "r"(dst), "l"(src));
        }
    };

    ld_stage(0, 0);
    asm volatile("cp.async.commit_group;\n" ::);
    if (KT > 1) ld_stage(1, 64);
    asm volatile("cp.async.commit_group;\n" ::);

    int buf = 0;
    for (int kt = 0; kt < KT; kt++) {
        asm volatile("cp.async.wait_group 1;\n" ::);
        __syncthreads();

        if (kt + 2 < KT) {
            int nb = buf + 2; if (nb >= N_STG) nb -= N_STG;
            ld_stage(nb, (kt + 2) * 64);
        }
        asm volatile("cp.async.commit_group;\n" ::);

        const __half* As = smh + buf * STGH;
        const __half* Bs = As + A_SZH;

#pragma unroll
        for (int ks = 0; ks < 4; ks++) {
            const int kk = ks * 16;
            unsigned af[4][4];
#pragma unroll
            for (int mt = 0; mt < 4; mt++) {
                int r = wm * 64 + mt * 16 + a_r;
                ldsm_x4(af[mt][0], af[mt][1], af[mt][2], af[mt][3],
                        &As[r * A_STR + kk + a_c]);
            }
            unsigned bf[4][2];
#pragma unroll
            for (int ntp = 0; ntp < 2; ntp++) {
                ldsm_x4_t(bf[ntp * 2][0], bf[ntp * 2][1], bf[ntp * 2 + 1][0], bf[ntp * 2 + 1][1],
                          &Bs[(kk + bt_r) * B_STR + wn * 32 + ntp * 16 + bt_c]);
            }
#pragma unroll
            for (int mt = 0; mt < 4; mt++)
#pragma unroll
                for (int nt = 0; nt < 4; nt++)
                    mma_f16(acc[mt][nt], af[mt], bf[nt]);
        }
        if (++buf >= N_STG) buf -= N_STG;
    }

#pragma unroll
    for (int mt = 0; mt < 4; mt++) {
#pragma unroll
        for (int nt = 0; nt < 4; nt++) {
            int col = col0 + wn * 32 + nt * 8 + tig * 2;
            float b0 = bias[col], b1 = bias[col + 1];
#pragma unroll
            for (int half_i = 0; half_i < 2; half_i++) {
                int row = row0 + wm * 64 + mt * 16 + gid + half_i * 8;
                float v0 = acc[mt][nt][half_i * 2 + 0] + b0;
                float v1 = acc[mt][nt][half_i * 2 + 1] + b1;
                if (do_gelu) {
                    float u0 = v0, u1 = v1;
                    v0 = 0.5f * u0 * (1.0f + tanhf(0.7978845608028654f * (u0 + 0.044715f * u0 * u0 * u0)));
                    v1 = 0.5f * u1 * (1.0f + tanhf(0.7978845608028654f * (u1 + 0.044715f * u1 * u1 * u1)));
                }
                if (out_half) {
                    *reinterpret_cast<__half2*>(&((__half*)Cv)[(size_t)row * N + col]) =
                        __floats2half2_rn(v0, v1);
                } else {
                    *reinterpret_cast<float2*>(&((float*)Cv)[(size_t)row * N + col]) =
                        make_float2(v0, v1);
                }
            }
        }
    }
}

// ---------------- elementwise fp32 -> fp16 ---------------------------------------
__global__ __launch_bounds__(256)
void conv_half(const float* __restrict__ in, __half* __restrict__ out)
{
    int i = blockIdx.x * 256 + threadIdx.x;
    float2 v = reinterpret_cast<const float2*>(in)[i];
    reinterpret_cast<__half2*>(out)[i] = __floats2half2_rn(v.x, v.y);
}

// ---------------- Flash attention, fp16 MMA, register-resident S/P --------------
#define AT_STR 72
#define AT_Q_SZ (128 * AT_STR)
#define AT_KV_SZ (64 * AT_STR)
#define AT_STG (2 * AT_KV_SZ)
#define AT_NSTG 3
#define AT_SMEM ((AT_Q_SZ + AT_NSTG * AT_STG) * 2)   // 73728 B

__global__ __launch_bounds__(256)
void attn_h(const __half* __restrict__ qkv, const int* __restrict__ lengths,
            __half* __restrict__ aout)
{
    extern __shared__ __half sa[];
    __half* Qh = sa;

    const int b   = blockIdx.z;
    const int t0  = blockIdx.x * 128;
    const int len = lengths[b];
    if (t0 >= len) return;

    const int tid  = threadIdx.x;
    const int wid  = tid >> 5;
    const int lane = tid & 31;
    const int gid  = lane >> 2;
    const int tig  = lane & 3;
    const int h    = blockIdx.y;
    const size_t bt0 = (size_t)b * TT + t0;
    const size_t btb = (size_t)b * TT;
    const int qoff = h * DH;
    const int koff = DD + h * DH;
    const int voff = 2 * DD + h * DH;

#pragma unroll
    for (int l = 0; l < 4; l++) {
        int idx = tid + l * 256;
        int q  = idx >> 3;
        int d  = (idx & 7) * 8;
        *reinterpret_cast<float4*>(&Qh[q * AT_STR + d]) =
            *reinterpret_cast<const float4*>(&qkv[(bt0 + q) * 2304 + qoff + d]);
    }

    auto ld_kv = [&](int s, int k0) {
        __half* Kh = sa + AT_Q_SZ + s * AT_STG;
        __half* Vh = Kh + AT_KV_SZ;
#pragma unroll
        for (int l = 0; l < 2; l++) {
            int idx = tid + l * 256;
            int r  = idx >> 3;
            int d  = (idx & 7) * 8;
            unsigned dk = (unsigned)__cvta_generic_to_shared(&Kh[r * AT_STR + d]);
            unsigned dv = (unsigned)__cvta_generic_to_shared(&Vh[r * AT_STR + d]);
            const __half* sk = &qkv[(btb + k0 + r) * 2304 + koff + d];
            const __half* sv = &qkv[(btb + k0 + r) * 2304 + voff + d];
            asm volatile("cp.async.cg.shared.global [%0], [%1], 16;\n" :: "r"(dk), "l"(sk));
            asm volatile("cp.async.cg.shared.global [%0], [%1], 16;\n" :: "r"(dv), "l"(sv));
        }
    };

    const int ntiles = (len + 63) >> 6;

    ld_kv(0, 0);
    asm volatile("cp.async.commit_group;\n" ::);
    if (ntiles > 1) ld_kv(1, 64);
    asm volatile("cp.async.commit_group;\n" ::);
    __syncthreads();

    unsigned qf[4][4];
    {
        int r = wid * 16 + (lane & 15);
        int c = (lane >> 4) * 8;
#pragma unroll
        for (int kc = 0; kc < 4; kc++)
            ldsm_x4(qf[kc][0], qf[kc][1], qf[kc][2], qf[kc][3],
                    &Qh[r * AT_STR + kc * 16 + c]);
    }

    float o[8][4];
#pragma unroll
    for (int j = 0; j < 8; j++)
#pragma unroll
        for (int c = 0; c < 4; c++) o[j][c] = 0.f;
    float m0 = -1e30f, m1 = -1e30f, l0 = 0.f, l1 = 0.f;

    const int b_r = ((lane >> 4) & 1) * 8 + (lane & 7);
    const int b_c = ((lane >> 3) & 1) * 8;
    const int v_tI = lane >> 3;
    const int v_r  = (v_tI & 1) * 8 + (lane & 7);
    const int v_c  = (v_tI >> 1) * 8;

    int sbuf = 0;
    for (int kt = 0; kt < ntiles; kt++) {
        const int k0 = kt * 64;
        asm volatile("cp.async.wait_group 1;\n" ::);
        __syncthreads();
        if (kt + 2 < ntiles) {
            int nb = sbuf + 2; if (nb >= AT_NSTG) nb -= AT_NSTG;
            ld_kv(nb, k0 + 128);
        }
        asm volatile("cp.async.commit_group;\n" ::);

        const __half* Kh = sa + AT_Q_SZ + sbuf * AT_STG;
        const __half* Vh = Kh + AT_KV_SZ;
        if (++sbuf >= AT_NSTG) sbuf -= AT_NSTG;

        float s[8][4];
#pragma unroll
        for (int j = 0; j < 8; j++)
#pragma unroll
            for (int c = 0; c < 4; c++) s[j][c] = 0.f;

#pragma unroll
        for (int kc = 0; kc < 4; kc++) {
            unsigned kf[8][2];
#pragma unroll
            for (int ntp = 0; ntp < 4; ntp++) {
                int n = ntp * 16 + b_r;
                ldsm_x4(kf[ntp * 2][0], kf[ntp * 2][1], kf[ntp * 2 + 1][0], kf[ntp * 2 + 1][1],
                        &Kh[n * AT_STR + kc * 16 + b_c]);
            }
#pragma unroll
            for (int j = 0; j < 8; j++)
                mma_f16(s[j], qf[kc], kf[j]);
        }

#pragma unroll
        for (int j = 0; j < 8; j++) {
            int kg = k0 + j * 8 + tig * 2;
            if (kg     >= len) { s[j][0] = -1e30f; s[j][2] = -1e30f; }
            if (kg + 1 >= len) { s[j][1] = -1e30f; s[j][3] = -1e30f; }
        }
        float mx0 = -1e30f, mx1 = -1e30f;
#pragma unroll
        for (int j = 0; j < 8; j++) {
            mx0 = fmaxf(mx0, fmaxf(s[j][0], s[j][1]));
            mx1 = fmaxf(mx1, fmaxf(s[j][2], s[j][3]));
        }
        mx0 = fmaxf(mx0, __shfl_xor_sync(0xffffffffu, mx0, 1));
        mx0 = fmaxf(mx0, __shfl_xor_sync(0xffffffffu, mx0, 2));
        mx1 = fmaxf(mx1, __shfl_xor_sync(0xffffffffu, mx1, 1));
        mx1 = fmaxf(mx1, __shfl_xor_sync(0xffffffffu, mx1, 2));
        float mn0 = fmaxf(m0, mx0), mn1 = fmaxf(m1, mx1);
        float sc0 = __expf(m0 - mn0), sc1 = __expf(m1 - mn1);

        float sum0 = 0.f, sum1 = 0.f;
        unsigned pf[4][4];
#pragma unroll
        for (int kc = 0; kc < 4; kc++) {
            int j0 = kc * 2, j1 = kc * 2 + 1;
            float e00 = __expf(s[j0][0] - mn0), e01 = __expf(s[j0][1] - mn0);
            float e10 = __expf(s[j0][2] - mn1), e11 = __expf(s[j0][3] - mn1);
            float f00 = __expf(s[j1][0] - mn0), f01 = __expf(s[j1][1] - mn0);
            float f10 = __expf(s[j1][2] - mn1), f11 = __expf(s[j1][3] - mn1);
            sum0 += e00 + e01 + f00 + f01;
            sum1 += e10 + e11 + f10 + f11;
            pf[kc][0] = h2pack(e00, e01);
            pf[kc][1] = h2pack(e10, e11);
            pf[kc][2] = h2pack(f00, f01);
            pf[kc][3] = h2pack(f10, f11);
        }
        sum0 += __shfl_xor_sync(0xffffffffu, sum0, 1);
        sum0 += __shfl_xor_sync(0xffffffffu, sum0, 2);
        sum1 += __shfl_xor_sync(0xffffffffu, sum1, 1);
        sum1 += __shfl_xor_sync(0xffffffffu, sum1, 2);
        l0 = l0 * sc0 + sum0;
        l1 = l1 * sc1 + sum1;
        m0 = mn0; m1 = mn1;

#pragma unroll
        for (int j = 0; j < 8; j++) {
            o[j][0] *= sc0; o[j][1] *= sc0;
            o[j][2] *= sc1; o[j][3] *= sc1;
        }

#pragma unroll
        for (int kc = 0; kc < 4; kc++) {
            unsigned vf[8][2];
#pragma unroll
            for (int ntp = 0; ntp < 4; ntp++) {
                ldsm_x4_t(vf[ntp * 2][0], vf[ntp * 2][1], vf[ntp * 2 + 1][0], vf[ntp * 2 + 1][1],
                          &Vh[(kc * 16 + v_r) * AT_STR + ntp * 16 + v_c]);
            }
#pragma unroll
            for (int j = 0; j < 8; j++)
                mma_f16(o[j], pf[kc], vf[j]);
        }
    }

    const int tq0 = t0 + wid * 16 + gid;
    const int tq1 = tq0 + 8;
    const float inv0 = (tq0 < len) ? (1.f / l0) : 0.f;
    const float inv1 = (tq1 < len) ? (1.f / l1) : 0.f;
#pragma unroll
    for (int j = 0; j < 8; j++) {
        int col = h * DH + j * 8 + tig * 2;
        *reinterpret_cast<__half2*>(&aout[(btb + tq0) * DD + col]) =
            __floats2half2_rn(o[j][0] * inv0, o[j][1] * inv0);
        *reinterpret_cast<__half2*>(&aout[(btb + tq1) * DD + col]) =
            __floats2half2_rn(o[j][2] * inv1, o[j][3] * inv1);
    }
}

// ---------------- residual + LayerNorm + mask (+ optional fp16 twin) ------------
__global__ __launch_bounds__(256)
void ln_kernel(const float* __restrict__ a, const float* __restrict__ r,
               const float* __restrict__ g, const float* __restrict__ beta,
               const int* __restrict__ lengths, float* __restrict__ out,
               __half* __restrict__ outh, int write_h)
{
    const int row = blockIdx.x;
    const int t = row & (TT - 1);
    const int bi = row >> 11;
    const float maskv = (t < lengths[bi]) ? 1.f : 0.f;
    const float* pa = a + (size_t)row * DD;
    const float* pr = r + (size_t)row * DD;

    float s = 0.f, s2 = 0.f;
    for (int i = threadIdx.x; i < DD; i += 256) {
        float v = pa[i] + pr[i];
        s += v; s2 += v * v;
    }
#pragma unroll
    for (int o = 16; o; o >>= 1) {
        s  += __shfl_down_sync(0xffffffffu, s,  o);
        s2 += __shfl_down_sync(0xffffffffu, s2, o);
    }
    __shared__ float ws[8], ws2[8];
    int w = threadIdx.x >> 5, lane = threadIdx.x & 31;
    if (lane == 0) { ws[w] = s; ws2[w] = s2; }
    __syncthreads();
    if (threadIdx.x == 0) {
        float S = 0.f, S2 = 0.f;
        for (int i = 0; i < 8; i++) { S += ws[i]; S2 += ws2[i]; }
        ws[0] = S; ws2[0] = S2;
    }
    __syncthreads();
    const float mu = ws[0] * (1.f / DD);
    const float var = ws2[0] * (1.f / DD) - mu * mu;
    const float rstd = rsqrtf(var + 1e-5f);
    for (int i = threadIdx.x; i < DD; i += 256) {
        float v = pa[i] + pr[i];
        float y = ((v - mu) * rstd * g[i] + beta[i]) * maskv;
        out[(size_t)row * DD + i] = y;
        if (write_h) outh[(size_t)row * DD + i] = __float2half(y);
    }
}

// ---------------- launcher ------------------------------------------------------
extern "C" void kernel_launch(void* const* d_in, const int* in_sizes, int n_in,
                              void* d_out, int out_size)
{
    const float* x      = (const float*)d_in[0];
    const int*   lens   = (const int*)  d_in[1];
    const float* w_qkv  = (const float*)d_in[2];
    const float* b_qkv  = (const float*)d_in[3];
    const float* w_proj = (const float*)d_in[4];
    const float* b_proj = (const float*)d_in[5];
    const float* ln1_g  = (const float*)d_in[6];
    const float* ln1_b  = (const float*)d_in[7];
    const float* w_fc   = (const float*)d_in[8];
    const float* b_fc   = (const float*)d_in[9];
    const float* w_out  = (const float*)d_in[10];
    const float* b_out  = (const float*)d_in[11];
    const float* ln2_g  = (const float*)d_in[12];
    const float* ln2_b  = (const float*)d_in[13];
    float* out = (float*)d_out;

    float  *p_proj, *p_n, *p_m;
    __half *p_xh, *p_qkvh, *p_attnh, *p_nh, *p_h1h;
    __half *p_wqkvh, *p_wprojh, *p_wfch, *p_wouth;
    cudaGetSymbolAddress((void**)&p_proj, g_proj);
    cudaGetSymbolAddress((void**)&p_n,    g_n);
    cudaGetSymbolAddress((void**)&p_m,    g_m);
    cudaGetSymbolAddress((void**)&p_xh,    g_xh);
    cudaGetSymbolAddress((void**)&p_qkvh,  g_qkvh);
    cudaGetSymbolAddress((void**)&p_attnh, g_attnh);
    cudaGetSymbolAddress((void**)&p_nh,    g_nh);
    cudaGetSymbolAddress((void**)&p_h1h,   g_h1h);
    cudaGetSymbolAddress((void**)&p_wqkvh,  g_wqkvh);
    cudaGetSymbolAddress((void**)&p_wprojh, g_wprojh);
    cudaGetSymbolAddress((void**)&p_wfch,   g_wfch);
    cudaGetSymbolAddress((void**)&p_wouth,  g_wouth);

    cudaFuncSetAttribute(gemm_h, cudaFuncAttributeMaxDynamicSharedMemorySize, GEMMH_SMEM);
    cudaFuncSetAttribute(attn_h, cudaFuncAttributeMaxDynamicSharedMemorySize, AT_SMEM);

    // 0) elementwise fp32->fp16 converts
    conv_half<<<(768 * 2304 / 2) / 256, 256>>>(w_qkv,  p_wqkvh);
    conv_half<<<(768 * 768  / 2) / 256, 256>>>(w_proj, p_wprojh);
    conv_half<<<(768 * 3072 / 2) / 256, 256>>>(w_fc,   p_wfch);
    conv_half<<<(3072 * 768 / 2) / 256, 256>>>(w_out,  p_wouth);
    conv_half<<<(BT * DD / 2) / 256, 256>>>(x, p_xh);

    // 1) qkv = x @ w_qkv + b_qkv                [4096, 2304] fp16
    gemm_h<<<dim3(2304 / 128, BT / 128), 256, GEMMH_SMEM>>>(p_xh, p_wqkvh, b_qkv, p_qkvh, lens, BT, 2304, DD, 0, 1);

    // 2) attention (fp16 MMA, register softmax)  [4096, 768] fp16
    attn_h<<<dim3(TT / 128, HH, BB), 256, AT_SMEM>>>(p_qkvh, lens, p_attnh);

    // 3) proj = attn @ w_proj + b_proj          [4096, 768] fp32
    gemm_h<<<dim3(DD / 128, BT / 128), 256, GEMMH_SMEM>>>(p_attnh, p_wprojh, b_proj, p_proj, lens, BT, DD, DD, 0, 0);

    // 4) n = LN(x + proj) * mask  (+ fp16 twin)
    ln_kernel<<<BT, 256>>>(x, p_proj, ln1_g, ln1_b, lens, p_n, p_nh, 1);

    // 5) h1 = gelu(n @ w_fc + b_fc)             [4096, 3072] fp16
    gemm_h<<<dim3(3072 / 128, BT / 128), 256, GEMMH_SMEM>>>(p_nh, p_wfch, b_fc, p_h1h, lens, BT, 3072, DD, 1, 1);

    // 6) m = h1 @ w_out + b_out                 [4096, 768] fp32
    gemm_h<<<dim3(DD / 128, BT / 128), 256, GEMMH_SMEM>>>(p_h1h, p_wouth, b_out, p_m, lens, BT, DD, 3072, 0, 0);

    // 7) out = LN(n + m) * mask
    ln_kernel<<<BT, 256>>>(p_n, p_m, ln2_g, ln2_b, lens, out, p_nh, 0);
}

// round 14
// speedup vs baseline: 1.2094x; 1.0792x over previous
#include <cuda_runtime.h>
#include <cuda_fp16.h>
#include <cstdint>

#define BB 2
#define TT 2048
#define DD 768
#define HH 12
#define DH 64
#define BT (BB*TT)

// ---------------- scratch (static device arrays; zero-initialized) --------------
__device__ float  g_proj[(size_t)2 * BT * DD];   // 2 split-K partials
__device__ float  g_n   [(size_t)BT * DD];
__device__ float  g_m   [(size_t)2 * BT * DD];   // 2 split-K partials
__device__ __half g_xh   [(size_t)BT * DD];
__device__ __half g_qkvh [(size_t)BT * 2304];
__device__ __half g_attnh[(size_t)BT * DD];
__device__ __half g_nh   [(size_t)BT * DD];
__device__ __half g_h1h  [(size_t)BT * 3072];
// fp16 weights, natural [K][N] layout
__device__ __half g_wqkvh [(size_t)768 * 2304];
__device__ __half g_wprojh[(size_t)768 * 768];
__device__ __half g_wfch  [(size_t)768 * 3072];
__device__ __half g_wouth [(size_t)3072 * 768];

__device__ __forceinline__ void mma_f16(float* c, const unsigned* a, const unsigned* b) {
    asm volatile(
        "mma.sync.aligned.m16n8k16.row.col.f32.f16.f16.f32 "
        "{%0,%1,%2,%3}, {%4,%5,%6,%7}, {%8,%9}, {%0,%1,%2,%3};"
        : "+f"(c[0]), "+f"(c[1]), "+f"(c[2]), "+f"(c[3])
        : "r"(a[0]), "r"(a[1]), "r"(a[2]), "r"(a[3]), "r"(b[0]), "r"(b[1]));
}

__device__ __forceinline__ void ldsm_x4(unsigned& r0, unsigned& r1, unsigned& r2, unsigned& r3,
                                        const __half* p) {
    unsigned addr = (unsigned)__cvta_generic_to_shared(p);
    asm volatile("ldmatrix.sync.aligned.m8n8.x4.shared.b16 {%0,%1,%2,%3}, [%4];"
                 : "=r"(r0), "=r"(r1), "=r"(r2), "=r"(r3) : "r"(addr));
}

__device__ __forceinline__ void ldsm_x4_t(unsigned& r0, unsigned& r1, unsigned& r2, unsigned& r3,
                                          const __half* p) {
    unsigned addr = (unsigned)__cvta_generic_to_shared(p);
    asm volatile("ldmatrix.sync.aligned.m8n8.x4.trans.shared.b16 {%0,%1,%2,%3}, [%4];"
                 : "=r"(r0), "=r"(r1), "=r"(r2), "=r"(r3) : "r"(addr));
}

__device__ __forceinline__ unsigned h2pack(float a, float b) {
    __half2 h = __floats2half2_rn(a, b);
    return *reinterpret_cast<unsigned*>(&h);
}

// ---------------- fp16 tensor-core GEMM, BK=64, 3-stage, in-kernel split-K ------
// C[z][M,N] += Ah[M, z*K .. z*K+K) @ Wh[z*K .., N]. bias added by z==0 only.
// BM=128 BN=128 BK=64, 256 threads = 8 warps (2x4), warp tile 64x32.
#define A_STR 72
#define A_SZH (128 * A_STR)
#define B_STR 136
#define B_SZH (64 * B_STR)
#define STGH (A_SZH + B_SZH)
#define N_STG 3
#define GEMMH_SMEM (N_STG * STGH * 2)   // 107520 B

__global__ __launch_bounds__(256)
void gemm_h(const __half* __restrict__ Ah, const __half* __restrict__ Wh,
            const float* __restrict__ bias, void* __restrict__ Cv,
            const int* __restrict__ lengths,
            int M, int N, int K, int lda, int do_gelu, int out_half)
{
    extern __shared__ __half smh[];

    const int row0 = blockIdx.y * 128;
    if ((row0 & (TT - 1)) >= lengths[row0 >> 11]) return;   // ragged skip

    const int z      = blockIdx.z;
    const int k_base = z * K;
    const int do_bias = (z == 0);

    const int tid  = threadIdx.x;
    const int wid  = tid >> 5;
    const int lane = tid & 31;
    const int gid  = lane >> 2;
    const int tig  = lane & 3;
    const int wm   = wid >> 2;
    const int wn   = wid & 3;
    const int col0 = blockIdx.x * 128;

    const int a_r  = (lane & 15);
    const int a_c  = (lane >> 4) * 8;
    const int tI   = lane >> 3;
    const int bt_r = (tI & 1) * 8 + (lane & 7);
    const int bt_c = (tI >> 1) * 8;

    float acc[4][4][4];
#pragma unroll
    for (int mt = 0; mt < 4; mt++)
#pragma unroll
        for (int nt = 0; nt < 4; nt++)
#pragma unroll
            for (int c = 0; c < 4; c++) acc[mt][nt][c] = 0.f;

    const int KT = K >> 6;

    auto ld_stage = [&](int s, int k0) {
        __half* As = smh + s * STGH;
        __half* Bs = As + A_SZH;
#pragma unroll
        for (int l = 0; l < 4; l++) {
            int ci = tid + l * 256;
            int r  = ci >> 3;
            int cc = (ci & 7) * 8;
            unsigned dst = (unsigned)__cvta_generic_to_shared(&As[r * A_STR + cc]);
            const __half* src = &Ah[(size_t)(row0 + r) * lda + k_base + k0 + cc];
            asm volatile("cp.async.cg.shared.global [%0], [%1], 16;\n" :: "r"(dst), "l"(src));
        }
#pragma unroll
        for (int l = 0; l < 4; l++) {
            int ci = tid + l * 256;
            int r  = ci >> 4;
            int cc = (ci & 15) * 8;
            unsigned dst = (unsigned)__cvta_generic_to_shared(&Bs[r * B_STR + cc]);
            const __half* src = &Wh[(size_t)(k_base + k0 + r) * N + col0 + cc];
            asm volatile("cp.async.cg.shared.global [%0], [%1], 16;\n" :: "r"(dst), "l"(src));
        }
    };

    ld_stage(0, 0);
    asm volatile("cp.async.commit_group;\n" ::);
    if (KT > 1) ld_stage(1, 64);
    asm volatile("cp.async.commit_group;\n" ::);

    int buf = 0;
    for (int kt = 0; kt < KT; kt++) {
        asm volatile("cp.async.wait_group 1;\n" ::);
        __syncthreads();

        if (kt + 2 < KT) {
            int nb = buf + 2; if (nb >= N_STG) nb -= N_STG;
            ld_stage(nb, (kt + 2) * 64);
        }
        asm volatile("cp.async.commit_group;\n" ::);

        const __half* As = smh + buf * STGH;
        const __half* Bs = As + A_SZH;

#pragma unroll
        for (int ks = 0; ks < 4; ks++) {
            const int kk = ks * 16;
            unsigned af[4][4];
#pragma unroll
            for (int mt = 0; mt < 4; mt++) {
                int r = wm * 64 + mt * 16 + a_r;
                ldsm_x4(af[mt][0], af[mt][1], af[mt][2], af[mt][3],
                        &As[r * A_STR + kk + a_c]);
            }
            unsigned bf[4][2];
#pragma unroll
            for (int ntp = 0; ntp < 2; ntp++) {
                ldsm_x4_t(bf[ntp * 2][0], bf[ntp * 2][1], bf[ntp * 2 + 1][0], bf[ntp * 2 + 1][1],
                          &Bs[(kk + bt_r) * B_STR + wn * 32 + ntp * 16 + bt_c]);
            }
#pragma unroll
            for (int mt = 0; mt < 4; mt++)
#pragma unroll
                for (int nt = 0; nt < 4; nt++)
                    mma_f16(acc[mt][nt], af[mt], bf[nt]);
        }
        if (++buf >= N_STG) buf -= N_STG;
    }

#pragma unroll
    for (int mt = 0; mt < 4; mt++) {
#pragma unroll
        for (int nt = 0; nt < 4; nt++) {
            int col = col0 + wn * 32 + nt * 8 + tig * 2;
            float b0 = do_bias ? bias[col] : 0.f;
            float b1 = do_bias ? bias[col + 1] : 0.f;
#pragma unroll
            for (int half_i = 0; half_i < 2; half_i++) {
                int row = row0 + wm * 64 + mt * 16 + gid + half_i * 8;
                float v0 = acc[mt][nt][half_i * 2 + 0] + b0;
                float v1 = acc[mt][nt][half_i * 2 + 1] + b1;
                if (do_gelu) {
                    float u0 = v0, u1 = v1;
                    v0 = 0.5f * u0 * (1.0f + tanhf(0.7978845608028654f * (u0 + 0.044715f * u0 * u0 * u0)));
                    v1 = 0.5f * u1 * (1.0f + tanhf(0.7978845608028654f * (u1 + 0.044715f * u1 * u1 * u1)));
                }
                if (out_half) {
                    *reinterpret_cast<__half2*>(&((__half*)Cv)[(size_t)row * N + col]) =
                        __floats2half2_rn(v0, v1);
                } else {
                    float* Cz = (float*)Cv + (size_t)z * M * N;
                    *reinterpret_cast<float2*>(&Cz[(size_t)row * N + col]) =
                        make_float2(v0, v1);
                }
            }
        }
    }
}

// ---------------- fused fp32 -> fp16 converts (all 5 tensors, 1 launch) ---------
#define CV0 884736        // w_qkv  768*2304/2
#define CV1 (CV0 + 294912)    // w_proj 768*768/2
#define CV2 (CV1 + 1179648)   // w_fc   768*3072/2
#define CV3 (CV2 + 1179648)   // w_out  3072*768/2
#define CV4 (CV3 + 1572864)   // x      BT*768/2
__global__ __launch_bounds__(256)
void conv_all(const float* __restrict__ w_qkv, const float* __restrict__ w_proj,
              const float* __restrict__ w_fc,  const float* __restrict__ w_out,
              const float* __restrict__ x,
              __half* __restrict__ o_qkv, __half* __restrict__ o_proj,
              __half* __restrict__ o_fc,  __half* __restrict__ o_out,
              __half* __restrict__ o_x)
{
    int i = blockIdx.x * 256 + threadIdx.x;
    const float2* src;
    __half2* dst;
    int off;
    if (i < CV0)      { src = (const float2*)w_qkv;  dst = (__half2*)o_qkv;  off = 0;   }
    else if (i < CV1) { src = (const float2*)w_proj; dst = (__half2*)o_proj; off = CV0; }
    else if (i < CV2) { src = (const float2*)w_fc;   dst = (__half2*)o_fc;   off = CV1; }
    else if (i < CV3) { src = (const float2*)w_out;  dst = (__half2*)o_out;  off = CV2; }
    else              { src = (const float2*)x;      dst = (__half2*)o_x;    off = CV3; }
    int j = i - off;
    float2 v = src[j];
    dst[j] = __floats2half2_rn(v.x, v.y);
}

// ---------------- Flash attention, fp16 MMA, register-resident S/P --------------
#define AT_STR 72
#define AT_Q_SZ (128 * AT_STR)
#define AT_KV_SZ (64 * AT_STR)
#define AT_STG (2 * AT_KV_SZ)
#define AT_NSTG 3
#define AT_SMEM ((AT_Q_SZ + AT_NSTG * AT_STG) * 2)   // 73728 B

__global__ __launch_bounds__(256)
void attn_h(const __half* __restrict__ qkv, const int* __restrict__ lengths,
            __half* __restrict__ aout)
{
    extern __shared__ __half sa[];
    __half* Qh = sa;

    const int b   = blockIdx.z;
    const int t0  = blockIdx.x * 128;
    const int len = lengths[b];
    if (t0 >= len) return;

    const int tid  = threadIdx.x;
    const int wid  = tid >> 5;
    const int lane = tid & 31;
    const int gid  = lane >> 2;
    const int tig  = lane & 3;
    const int h    = blockIdx.y;
    const size_t bt0 = (size_t)b * TT + t0;
    const size_t btb = (size_t)b * TT;
    const int qoff = h * DH;
    const int koff = DD + h * DH;
    const int voff = 2 * DD + h * DH;

#pragma unroll
    for (int l = 0; l < 4; l++) {
        int idx = tid + l * 256;
        int q  = idx >> 3;
        int d  = (idx & 7) * 8;
        *reinterpret_cast<float4*>(&Qh[q * AT_STR + d]) =
            *reinterpret_cast<const float4*>(&qkv[(bt0 + q) * 2304 + qoff + d]);
    }

    auto ld_kv = [&](int s, int k0) {
        __half* Kh = sa + AT_Q_SZ + s * AT_STG;
        __half* Vh = Kh + AT_KV_SZ;
#pragma unroll
        for (int l = 0; l < 2; l++) {
            int idx = tid + l * 256;
            int r  = idx >> 3;
            int d  = (idx & 7) * 8;
            unsigned dk = (unsigned)__cvta_generic_to_shared(&Kh[r * AT_STR + d]);
            unsigned dv = (unsigned)__cvta_generic_to_shared(&Vh[r * AT_STR + d]);
            const __half* sk = &qkv[(btb + k0 + r) * 2304 + koff + d];
            const __half* sv = &qkv[(btb + k0 + r) * 2304 + voff + d];
            asm volatile("cp.async.cg.shared.global [%0], [%1], 16;\n" :: "r"(dk), "l"(sk));
            asm volatile("cp.async.cg.shared.global [%0], [%1], 16;\n" :: "r"(dv), "l"(sv));
        }
    };

    const int ntiles = (len + 63) >> 6;

    ld_kv(0, 0);
    asm volatile("cp.async.commit_group;\n" ::);
    if (ntiles > 1) ld_kv(1, 64);
    asm volatile("cp.async.commit_group;\n" ::);
    __syncthreads();

    unsigned qf[4][4];
    {
        int r = wid * 16 + (lane & 15);
        int c = (lane >> 4) * 8;
#pragma unroll
        for (int kc = 0; kc < 4; kc++)
            ldsm_x4(qf[kc][0], qf[kc][1], qf[kc][2], qf[kc][3],
                    &Qh[r * AT_STR + kc * 16 + c]);
    }

    float o[8][4];
#pragma unroll
    for (int j = 0; j < 8; j++)
#pragma unroll
        for (int c = 0; c < 4; c++) o[j][c] = 0.f;
    float m0 = -1e30f, m1 = -1e30f, l0 = 0.f, l1 = 0.f;

    const int b_r = ((lane >> 4) & 1) * 8 + (lane & 7);
    const int b_c = ((lane >> 3) & 1) * 8;
    const int v_tI = lane >> 3;
    const int v_r  = (v_tI & 1) * 8 + (lane & 7);
    const int v_c  = (v_tI >> 1) * 8;

    int sbuf = 0;
    for (int kt = 0; kt < ntiles; kt++) {
        const int k0 = kt * 64;
        asm volatile("cp.async.wait_group 1;\n" ::);
        __syncthreads();
        if (kt + 2 < ntiles) {
            int nb = sbuf + 2; if (nb >= AT_NSTG) nb -= AT_NSTG;
            ld_kv(nb, k0 + 128);
        }
        asm volatile("cp.async.commit_group;\n" ::);

        const __half* Kh = sa + AT_Q_SZ + sbuf * AT_STG;
        const __half* Vh = Kh + AT_KV_SZ;
        if (++sbuf >= AT_NSTG) sbuf -= AT_NSTG;

        float s[8][4];
#pragma unroll
        for (int j = 0; j < 8; j++)
#pragma unroll
            for (int c = 0; c < 4; c++) s[j][c] = 0.f;

#pragma unroll
        for (int kc = 0; kc < 4; kc++) {
            unsigned kf[8][2];
#pragma unroll
            for (int ntp = 0; ntp < 4; ntp++) {
                int n = ntp * 16 + b_r;
                ldsm_x4(kf[ntp * 2][0], kf[ntp * 2][1], kf[ntp * 2 + 1][0], kf[ntp * 2 + 1][1],
                        &Kh[n * AT_STR + kc * 16 + b_c]);
            }
#pragma unroll
            for (int j = 0; j < 8; j++)
                mma_f16(s[j], qf[kc], kf[j]);
        }

#pragma unroll
        for (int j = 0; j < 8; j++) {
            int kg = k0 + j * 8 + tig * 2;
            if (kg     >= len) { s[j][0] = -1e30f; s[j][2] = -1e30f; }
            if (kg + 1 >= len) { s[j][1] = -1e30f; s[j][3] = -1e30f; }
        }
        float mx0 = -1e30f, mx1 = -1e30f;
#pragma unroll
        for (int j = 0; j < 8; j++) {
            mx0 = fmaxf(mx0, fmaxf(s[j][0], s[j][1]));
            mx1 = fmaxf(mx1, fmaxf(s[j][2], s[j][3]));
        }
        mx0 = fmaxf(mx0, __shfl_xor_sync(0xffffffffu, mx0, 1));
        mx0 = fmaxf(mx0, __shfl_xor_sync(0xffffffffu, mx0, 2));
        mx1 = fmaxf(mx1, __shfl_xor_sync(0xffffffffu, mx1, 1));
        mx1 = fmaxf(mx1, __shfl_xor_sync(0xffffffffu, mx1, 2));
        float mn0 = fmaxf(m0, mx0), mn1 = fmaxf(m1, mx1);
        float sc0 = __expf(m0 - mn0), sc1 = __expf(m1 - mn1);

        float sum0 = 0.f, sum1 = 0.f;
        unsigned pf[4][4];
#pragma unroll
        for (int kc = 0; kc < 4; kc++) {
            int j0 = kc * 2, j1 = kc * 2 + 1;
            float e00 = __expf(s[j0][0] - mn0), e01 = __expf(s[j0][1] - mn0);
            float e10 = __expf(s[j0][2] - mn1), e11 = __expf(s[j0][3] - mn1);
            float f00 = __expf(s[j1][0] - mn0), f01 = __expf(s[j1][1] - mn0);
            float f10 = __expf(s[j1][2] - mn1), f11 = __expf(s[j1][3] - mn1);
            sum0 += e00 + e01 + f00 + f01;
            sum1 += e10 + e11 + f10 + f11;
            pf[kc][0] = h2pack(e00, e01);
            pf[kc][1] = h2pack(e10, e11);
            pf[kc][2] = h2pack(f00, f01);
            pf[kc][3] = h2pack(f10, f11);
        }
        sum0 += __shfl_xor_sync(0xffffffffu, sum0, 1);
        sum0 += __shfl_xor_sync(0xffffffffu, sum0, 2);
        sum1 += __shfl_xor_sync(0xffffffffu, sum1, 1);
        sum1 += __shfl_xor_sync(0xffffffffu, sum1, 2);
        l0 = l0 * sc0 + sum0;
        l1 = l1 * sc1 + sum1;
        m0 = mn0; m1 = mn1;

#pragma unroll
        for (int j = 0; j < 8; j++) {
            o[j][0] *= sc0; o[j][1] *= sc0;
            o[j][2] *= sc1; o[j][3] *= sc1;
        }

#pragma unroll
        for (int kc = 0; kc < 4; kc++) {
            unsigned vf[8][2];
#pragma unroll
            for (int ntp = 0; ntp < 4; ntp++) {
                ldsm_x4_t(vf[ntp * 2][0], vf[ntp * 2][1], vf[ntp * 2 + 1][0], vf[ntp * 2 + 1][1],
                          &Vh[(kc * 16 + v_r) * AT_STR + ntp * 16 + v_c]);
            }
#pragma unroll
            for (int j = 0; j < 8; j++)
                mma_f16(o[j], pf[kc], vf[j]);
        }
    }

    const int tq0 = t0 + wid * 16 + gid;
    const int tq1 = tq0 + 8;
    const float inv0 = (tq0 < len) ? (1.f / l0) : 0.f;
    const float inv1 = (tq1 < len) ? (1.f / l1) : 0.f;
#pragma unroll
    for (int j = 0; j < 8; j++) {
        int col = h * DH + j * 8 + tig * 2;
        *reinterpret_cast<__half2*>(&aout[(btb + tq0) * DD + col]) =
            __floats2half2_rn(o[j][0] * inv0, o[j][1] * inv0);
        *reinterpret_cast<__half2*>(&aout[(btb + tq1) * DD + col]) =
            __floats2half2_rn(o[j][2] * inv1, o[j][3] * inv1);
    }
}

// ---------------- residual + LN + mask; r is 2-partial split-K sum --------------
__global__ __launch_bounds__(256)
void ln_kernel(const float* __restrict__ a, const float* __restrict__ r,
               const float* __restrict__ g, const float* __restrict__ beta,
               const int* __restrict__ lengths, float* __restrict__ out,
               __half* __restrict__ outh, int write_h)
{
    const int row = blockIdx.x;
    const int t = row & (TT - 1);
    const int bi = row >> 11;
    const float maskv = (t < lengths[bi]) ? 1.f : 0.f;
    const float* pa  = a + (size_t)row * DD;
    const float* pr  = r + (size_t)row * DD;
    const float* pr2 = r + (size_t)BT * DD + (size_t)row * DD;

    float s = 0.f, s2 = 0.f;
    for (int i = threadIdx.x; i < DD; i += 256) {
        float v = pa[i] + pr[i] + pr2[i];
        s += v; s2 += v * v;
    }
#pragma unroll
    for (int o = 16; o; o >>= 1) {
        s  += __shfl_down_sync(0xffffffffu, s,  o);
        s2 += __shfl_down_sync(0xffffffffu, s2, o);
    }
    __shared__ float ws[8], ws2[8];
    int w = threadIdx.x >> 5, lane = threadIdx.x & 31;
    if (lane == 0) { ws[w] = s; ws2[w] = s2; }
    __syncthreads();
    if (threadIdx.x == 0) {
        float S = 0.f, S2 = 0.f;
        for (int i = 0; i < 8; i++) { S += ws[i]; S2 += ws2[i]; }
        ws[0] = S; ws2[0] = S2;
    }
    __syncthreads();
    const float mu = ws[0] * (1.f / DD);
    const float var = ws2[0] * (1.f / DD) - mu * mu;
    const float rstd = rsqrtf(var + 1e-5f);
    for (int i = threadIdx.x; i < DD; i += 256) {
        float v = pa[i] + pr[i] + pr2[i];
        float y = ((v - mu) * rstd * g[i] + beta[i]) * maskv;
        out[(size_t)row * DD + i] = y;
        if (write_h) outh[(size_t)row * DD + i] = __float2half(y);
    }
}

// ---------------- launcher ------------------------------------------------------
extern "C" void kernel_launch(void* const* d_in, const int* in_sizes, int n_in,
                              void* d_out, int out_size)
{
    const float* x      = (const float*)d_in[0];
    const int*   lens   = (const int*)  d_in[1];
    const float* w_qkv  = (const float*)d_in[2];
    const float* b_qkv  = (const float*)d_in[3];
    const float* w_proj = (const float*)d_in[4];
    const float* b_proj = (const float*)d_in[5];
    const float* ln1_g  = (const float*)d_in[6];
    const float* ln1_b  = (const float*)d_in[7];
    const float* w_fc   = (const float*)d_in[8];
    const float* b_fc   = (const float*)d_in[9];
    const float* w_out  = (const float*)d_in[10];
    const float* b_out  = (const float*)d_in[11];
    const float* ln2_g  = (const float*)d_in[12];
    const float* ln2_b  = (const float*)d_in[13];
    float* out = (float*)d_out;

    float  *p_proj, *p_n, *p_m;
    __half *p_xh, *p_qkvh, *p_attnh, *p_nh, *p_h1h;
    __half *p_wqkvh, *p_wprojh, *p_wfch, *p_wouth;
    cudaGetSymbolAddress((void**)&p_proj, g_proj);
    cudaGetSymbolAddress((void**)&p_n,    g_n);
    cudaGetSymbolAddress((void**)&p_m,    g_m);
    cudaGetSymbolAddress((void**)&p_xh,    g_xh);
    cudaGetSymbolAddress((void**)&p_qkvh,  g_qkvh);
    cudaGetSymbolAddress((void**)&p_attnh, g_attnh);
    cudaGetSymbolAddress((void**)&p_nh,    g_nh);
    cudaGetSymbolAddress((void**)&p_h1h,   g_h1h);
    cudaGetSymbolAddress((void**)&p_wqkvh,  g_wqkvh);
    cudaGetSymbolAddress((void**)&p_wprojh, g_wprojh);
    cudaGetSymbolAddress((void**)&p_wfch,   g_wfch);
    cudaGetSymbolAddress((void**)&p_wouth,  g_wouth);

    cudaFuncSetAttribute(gemm_h, cudaFuncAttributeMaxDynamicSharedMemorySize, GEMMH_SMEM);
    cudaFuncSetAttribute(attn_h, cudaFuncAttributeMaxDynamicSharedMemorySize, AT_SMEM);

    // 0) fused fp32->fp16 converts (weights + x), one launch
    conv_all<<<CV4 / 256, 256>>>(w_qkv, w_proj, w_fc, w_out, x,
                                 p_wqkvh, p_wprojh, p_wfch, p_wouth, p_xh);

    // 1) qkv = x @ w_qkv + b_qkv                [4096, 2304] fp16
    gemm_h<<<dim3(2304 / 128, BT / 128, 1), 256, GEMMH_SMEM>>>(
        p_xh, p_wqkvh, b_qkv, p_qkvh, lens, BT, 2304, DD, DD, 0, 1);

    // 2) attention (fp16 MMA, register softmax)  [4096, 768] fp16
    attn_h<<<dim3(TT / 128, HH, BB), 256, AT_SMEM>>>(p_qkvh, lens, p_attnh);

    // 3) proj = attn @ w_proj (split-K=2, 2 fp32 partials)
    gemm_h<<<dim3(DD / 128, BT / 128, 2), 256, GEMMH_SMEM>>>(
        p_attnh, p_wprojh, b_proj, p_proj, lens, BT, DD, DD / 2, DD, 0, 0);

    // 4) n = LN(x + proj0 + proj1) * mask  (+ fp16 twin)
    ln_kernel<<<BT, 256>>>(x, p_proj, ln1_g, ln1_b, lens, p_n, p_nh, 1);

    // 5) h1 = gelu(n @ w_fc + b_fc)             [4096, 3072] fp16
    gemm_h<<<dim3(3072 / 128, BT / 128, 1), 256, GEMMH_SMEM>>>(
        p_nh, p_wfch, b_fc, p_h1h, lens, BT, 3072, DD, DD, 1, 1);

    // 6) m = h1 @ w_out (split-K=2, 2 fp32 partials)
    gemm_h<<<dim3(DD / 128, BT / 128, 2), 256, GEMMH_SMEM>>>(
        p_h1h, p_wouth, b_out, p_m, lens, BT, DD, 3072 / 2, 3072, 0, 0);

    // 7) out = LN(n + m0 + m1) * mask
    ln_kernel<<<BT, 256>>>(p_n, p_m, ln2_g, ln2_b, lens, out, p_nh, 0);
}

// round 15
// speedup vs baseline: 1.2218x; 1.0103x over previous
#include <cuda_runtime.h>
#include <cuda_fp16.h>
#include <cstdint>

#define BB 2
#define TT 2048
#define DD 768
#define HH 12
#define DH 64
#define BT (BB*TT)

// ---------------- scratch (static device arrays; zero-initialized) --------------
__device__ float  g_proj[(size_t)2 * BT * DD];   // 2 split-K partials
__device__ float  g_n   [(size_t)BT * DD];
__device__ float  g_m   [(size_t)2 * BT * DD];   // 2 split-K partials
__device__ __half g_xh   [(size_t)BT * DD];
__device__ __half g_qkvh [(size_t)BT * 2304];
__device__ __half g_attnh[(size_t)BT * DD];
__device__ __half g_nh   [(size_t)BT * DD];
__device__ __half g_h1h  [(size_t)BT * 3072];
// fp16 weights, natural [K][N] layout
__device__ __half g_wqkvh [(size_t)768 * 2304];
__device__ __half g_wprojh[(size_t)768 * 768];
__device__ __half g_wfch  [(size_t)768 * 3072];
__device__ __half g_wouth [(size_t)3072 * 768];

__device__ __forceinline__ void mma_f16(float* c, const unsigned* a, const unsigned* b) {
    asm volatile(
        "mma.sync.aligned.m16n8k16.row.col.f32.f16.f16.f32 "
        "{%0,%1,%2,%3}, {%4,%5,%6,%7}, {%8,%9}, {%0,%1,%2,%3};"
        : "+f"(c[0]), "+f"(c[1]), "+f"(c[2]), "+f"(c[3])
        : "r"(a[0]), "r"(a[1]), "r"(a[2]), "r"(a[3]), "r"(b[0]), "r"(b[1]));
}

__device__ __forceinline__ void ldsm_x4(unsigned& r0, unsigned& r1, unsigned& r2, unsigned& r3,
                                        const __half* p) {
    unsigned addr = (unsigned)__cvta_generic_to_shared(p);
    asm volatile("ldmatrix.sync.aligned.m8n8.x4.shared.b16 {%0,%1,%2,%3}, [%4];"
                 : "=r"(r0), "=r"(r1), "=r"(r2), "=r"(r3) : "r"(addr));
}

__device__ __forceinline__ void ldsm_x4_t(unsigned& r0, unsigned& r1, unsigned& r2, unsigned& r3,
                                          const __half* p) {
    unsigned addr = (unsigned)__cvta_generic_to_shared(p);
    asm volatile("ldmatrix.sync.aligned.m8n8.x4.trans.shared.b16 {%0,%1,%2,%3}, [%4];"
                 : "=r"(r0), "=r"(r1), "=r"(r2), "=r"(r3) : "r"(addr));
}

__device__ __forceinline__ unsigned h2pack(float a, float b) {
    __half2 h = __floats2half2_rn(a, b);
    return *reinterpret_cast<unsigned*>(&h);
}

// ---------------- fp16 GEMM: 128-thread CTA, BM=64 BN=128 BK=64, 2-stage --------
// 4 CTAs/SM -> 4 independent barrier domains; split-K via blockIdx.z.
#define GA_STR 72
#define GA_SZH (64 * GA_STR)            // 4608 halves
#define GB_STR 136
#define GB_SZH (64 * GB_STR)            // 8704 halves
#define GSTG (GA_SZH + GB_SZH)          // 13312 halves
#define GN_STG 2
#define GEMMH_SMEM (GN_STG * GSTG * 2)  // 53248 B

__global__ __launch_bounds__(128, 4)
void gemm_h(const __half* __restrict__ Ah, const __half* __restrict__ Wh,
            const float* __restrict__ bias, void* __restrict__ Cv,
            const int* __restrict__ lengths,
            int M, int N, int K, int lda, int do_gelu, int out_half)
{
    extern __shared__ __half smh[];

    const int row0 = blockIdx.y * 64;
    if ((row0 & (TT - 1)) >= lengths[row0 >> 11]) return;   // ragged skip

    const int z      = blockIdx.z;
    const int k_base = z * K;
    const int do_bias = (z == 0);

    const int tid  = threadIdx.x;
    const int wid  = tid >> 5;           // 0..3 : 32-col slab
    const int lane = tid & 31;
    const int gid  = lane >> 2;
    const int tig  = lane & 3;
    const int col0 = blockIdx.x * 128;

    const int a_r  = (lane & 15);
    const int a_c  = (lane >> 4) * 8;
    const int tI   = lane >> 3;
    const int bt_r = (tI & 1) * 8 + (lane & 7);
    const int bt_c = (tI >> 1) * 8;

    float acc[4][4][4];                  // [mt][nt][c]
#pragma unroll
    for (int mt = 0; mt < 4; mt++)
#pragma unroll
        for (int nt = 0; nt < 4; nt++)
#pragma unroll
            for (int c = 0; c < 4; c++) acc[mt][nt][c] = 0.f;

    const int KT = K >> 6;

    auto ld_stage = [&](int s, int k0) {
        __half* As = smh + s * GSTG;
        __half* Bs = As + GA_SZH;
        // A: 64x64 halves = 512 16B chunks, 4/thread
#pragma unroll
        for (int l = 0; l < 4; l++) {
            int ci = tid + l * 128;
            int r  = ci >> 3;               // 0..63
            int cc = (ci & 7) * 8;
            unsigned dst = (unsigned)__cvta_generic_to_shared(&As[r * GA_STR + cc]);
            const __half* src = &Ah[(size_t)(row0 + r) * lda + k_base + k0 + cc];
            asm volatile("cp.async.cg.shared.global [%0], [%1], 16;\n" :: "r"(dst), "l"(src));
        }
        // B: 64x128 halves = 1024 16B chunks, 8/thread
#pragma unroll
        for (int l = 0; l < 8; l++) {
            int ci = tid + l * 128;
            int r  = ci >> 4;               // 0..63 (k)
            int cc = (ci & 15) * 8;         // 0..120 (n)
            unsigned dst = (unsigned)__cvta_generic_to_shared(&Bs[r * GB_STR + cc]);
            const __half* src = &Wh[(size_t)(k_base + k0 + r) * N + col0 + cc];
            asm volatile("cp.async.cg.shared.global [%0], [%1], 16;\n" :: "r"(dst), "l"(src));
        }
    };

    ld_stage(0, 0);
    asm volatile("cp.async.commit_group;\n" ::);

    for (int kt = 0; kt < KT; kt++) {
        if (kt + 1 < KT) ld_stage((kt + 1) & 1, (kt + 1) * 64);
        asm volatile("cp.async.commit_group;\n" ::);
        asm volatile("cp.async.wait_group 1;\n" ::);
        __syncthreads();

        const __half* As = smh + (kt & 1) * GSTG;
        const __half* Bs = As + GA_SZH;

#pragma unroll
        for (int ks = 0; ks < 4; ks++) {
            const int kk = ks * 16;
            unsigned af[4][4];
#pragma unroll
            for (int mt = 0; mt < 4; mt++) {
                int r = mt * 16 + a_r;
                ldsm_x4(af[mt][0], af[mt][1], af[mt][2], af[mt][3],
                        &As[r * GA_STR + kk + a_c]);
            }
            unsigned bf[4][2];
#pragma unroll
            for (int ntp = 0; ntp < 2; ntp++) {
                ldsm_x4_t(bf[ntp * 2][0], bf[ntp * 2][1], bf[ntp * 2 + 1][0], bf[ntp * 2 + 1][1],
                          &Bs[(kk + bt_r) * GB_STR + wid * 32 + ntp * 16 + bt_c]);
            }
#pragma unroll
            for (int mt = 0; mt < 4; mt++)
#pragma unroll
                for (int nt = 0; nt < 4; nt++)
                    mma_f16(acc[mt][nt], af[mt], bf[nt]);
        }
        __syncthreads();   // protect buffer (kt&1) from next iteration's load
    }

#pragma unroll
    for (int mt = 0; mt < 4; mt++) {
#pragma unroll
        for (int nt = 0; nt < 4; nt++) {
            int col = col0 + wid * 32 + nt * 8 + tig * 2;
            float b0 = do_bias ? bias[col] : 0.f;
            float b1 = do_bias ? bias[col + 1] : 0.f;
#pragma unroll
            for (int half_i = 0; half_i < 2; half_i++) {
                int row = row0 + mt * 16 + gid + half_i * 8;
                float v0 = acc[mt][nt][half_i * 2 + 0] + b0;
                float v1 = acc[mt][nt][half_i * 2 + 1] + b1;
                if (do_gelu) {
                    float u0 = v0, u1 = v1;
                    v0 = 0.5f * u0 * (1.0f + tanhf(0.7978845608028654f * (u0 + 0.044715f * u0 * u0 * u0)));
                    v1 = 0.5f * u1 * (1.0f + tanhf(0.7978845608028654f * (u1 + 0.044715f * u1 * u1 * u1)));
                }
                if (out_half) {
                    *reinterpret_cast<__half2*>(&((__half*)Cv)[(size_t)row * N + col]) =
                        __floats2half2_rn(v0, v1);
                } else {
                    float* Cz = (float*)Cv + (size_t)z * M * N;
                    *reinterpret_cast<float2*>(&Cz[(size_t)row * N + col]) =
                        make_float2(v0, v1);
                }
            }
        }
    }
}

// ---------------- fused fp32 -> fp16 converts (all 5 tensors, 1 launch) ---------
#define CV0 884736            // w_qkv  768*2304/2
#define CV1 (CV0 + 294912)    // w_proj 768*768/2
#define CV2 (CV1 + 1179648)   // w_fc   768*3072/2
#define CV3 (CV2 + 1179648)   // w_out  3072*768/2
#define CV4 (CV3 + 1572864)   // x      BT*768/2
__global__ __launch_bounds__(256)
void conv_all(const float* __restrict__ w_qkv, const float* __restrict__ w_proj,
              const float* __restrict__ w_fc,  const float* __restrict__ w_out,
              const float* __restrict__ x,
              __half* __restrict__ o_qkv, __half* __restrict__ o_proj,
              __half* __restrict__ o_fc,  __half* __restrict__ o_out,
              __half* __restrict__ o_x)
{
    int i = blockIdx.x * 256 + threadIdx.x;
    const float2* src;
    __half2* dst;
    int off;
    if (i < CV0)      { src = (const float2*)w_qkv;  dst = (__half2*)o_qkv;  off = 0;   }
    else if (i < CV1) { src = (const float2*)w_proj; dst = (__half2*)o_proj; off = CV0; }
    else if (i < CV2) { src = (const float2*)w_fc;   dst = (__half2*)o_fc;   off = CV1; }
    else if (i < CV3) { src = (const float2*)w_out;  dst = (__half2*)o_out;  off = CV2; }
    else              { src = (const float2*)x;      dst = (__half2*)o_x;    off = CV3; }
    int j = i - off;
    float2 v = src[j];
    dst[j] = __floats2half2_rn(v.x, v.y);
}

// ---------------- Flash attention, fp16 MMA, register-resident S/P --------------
#define AT_STR 72
#define AT_Q_SZ (128 * AT_STR)
#define AT_KV_SZ (64 * AT_STR)
#define AT_STG (2 * AT_KV_SZ)
#define AT_NSTG 3
#define AT_SMEM ((AT_Q_SZ + AT_NSTG * AT_STG) * 2)   // 73728 B

__global__ __launch_bounds__(256)
void attn_h(const __half* __restrict__ qkv, const int* __restrict__ lengths,
            __half* __restrict__ aout)
{
    extern __shared__ __half sa[];
    __half* Qh = sa;

    const int b   = blockIdx.z;
    const int t0  = blockIdx.x * 128;
    const int len = lengths[b];
    if (t0 >= len) return;

    const int tid  = threadIdx.x;
    const int wid  = tid >> 5;
    const int lane = tid & 31;
    const int gid  = lane >> 2;
    const int tig  = lane & 3;
    const int h    = blockIdx.y;
    const size_t bt0 = (size_t)b * TT + t0;
    const size_t btb = (size_t)b * TT;
    const int qoff = h * DH;
    const int koff = DD + h * DH;
    const int voff = 2 * DD + h * DH;

#pragma unroll
    for (int l = 0; l < 4; l++) {
        int idx = tid + l * 256;
        int q  = idx >> 3;
        int d  = (idx & 7) * 8;
        *reinterpret_cast<float4*>(&Qh[q * AT_STR + d]) =
            *reinterpret_cast<const float4*>(&qkv[(bt0 + q) * 2304 + qoff + d]);
    }

    auto ld_kv = [&](int s, int k0) {
        __half* Kh = sa + AT_Q_SZ + s * AT_STG;
        __half* Vh = Kh + AT_KV_SZ;
#pragma unroll
        for (int l = 0; l < 2; l++) {
            int idx = tid + l * 256;
            int r  = idx >> 3;
            int d  = (idx & 7) * 8;
            unsigned dk = (unsigned)__cvta_generic_to_shared(&Kh[r * AT_STR + d]);
            unsigned dv = (unsigned)__cvta_generic_to_shared(&Vh[r * AT_STR + d]);
            const __half* sk = &qkv[(btb + k0 + r) * 2304 + koff + d];
            const __half* sv = &qkv[(btb + k0 + r) * 2304 + voff + d];
            asm volatile("cp.async.cg.shared.global [%0], [%1], 16;\n" :: "r"(dk), "l"(sk));
            asm volatile("cp.async.cg.shared.global [%0], [%1], 16;\n" :: "r"(dv), "l"(sv));
        }
    };

    const int ntiles = (len + 63) >> 6;

    ld_kv(0, 0);
    asm volatile("cp.async.commit_group;\n" ::);
    if (ntiles > 1) ld_kv(1, 64);
    asm volatile("cp.async.commit_group;\n" ::);
    __syncthreads();

    unsigned qf[4][4];
    {
        int r = wid * 16 + (lane & 15);
        int c = (lane >> 4) * 8;
#pragma unroll
        for (int kc = 0; kc < 4; kc++)
            ldsm_x4(qf[kc][0], qf[kc][1], qf[kc][2], qf[kc][3],
                    &Qh[r * AT_STR + kc * 16 + c]);
    }

    float o[8][4];
#pragma unroll
    for (int j = 0; j < 8; j++)
#pragma unroll
        for (int c = 0; c < 4; c++) o[j][c] = 0.f;
    float m0 = -1e30f, m1 = -1e30f, l0 = 0.f, l1 = 0.f;

    const int b_r = ((lane >> 4) & 1) * 8 + (lane & 7);
    const int b_c = ((lane >> 3) & 1) * 8;
    const int v_tI = lane >> 3;
    const int v_r  = (v_tI & 1) * 8 + (lane & 7);
    const int v_c  = (v_tI >> 1) * 8;

    int sbuf = 0;
    for (int kt = 0; kt < ntiles; kt++) {
        const int k0 = kt * 64;
        asm volatile("cp.async.wait_group 1;\n" ::);
        __syncthreads();
        if (kt + 2 < ntiles) {
            int nb = sbuf + 2; if (nb >= AT_NSTG) nb -= AT_NSTG;
            ld_kv(nb, k0 + 128);
        }
        asm volatile("cp.async.commit_group;\n" ::);

        const __half* Kh = sa + AT_Q_SZ + sbuf * AT_STG;
        const __half* Vh = Kh + AT_KV_SZ;
        if (++sbuf >= AT_NSTG) sbuf -= AT_NSTG;

        float s[8][4];
#pragma unroll
        for (int j = 0; j < 8; j++)
#pragma unroll
            for (int c = 0; c < 4; c++) s[j][c] = 0.f;

#pragma unroll
        for (int kc = 0; kc < 4; kc++) {
            unsigned kf[8][2];
#pragma unroll
            for (int ntp = 0; ntp < 4; ntp++) {
                int n = ntp * 16 + b_r;
                ldsm_x4(kf[ntp * 2][0], kf[ntp * 2][1], kf[ntp * 2 + 1][0], kf[ntp * 2 + 1][1],
                        &Kh[n * AT_STR + kc * 16 + b_c]);
            }
#pragma unroll
            for (int j = 0; j < 8; j++)
                mma_f16(s[j], qf[kc], kf[j]);
        }

#pragma unroll
        for (int j = 0; j < 8; j++) {
            int kg = k0 + j * 8 + tig * 2;
            if (kg     >= len) { s[j][0] = -1e30f; s[j][2] = -1e30f; }
            if (kg + 1 >= len) { s[j][1] = -1e30f; s[j][3] = -1e30f; }
        }
        float mx0 = -1e30f, mx1 = -1e30f;
#pragma unroll
        for (int j = 0; j < 8; j++) {
            mx0 = fmaxf(mx0, fmaxf(s[j][0], s[j][1]));
            mx1 = fmaxf(mx1, fmaxf(s[j][2], s[j][3]));
        }
        mx0 = fmaxf(mx0, __shfl_xor_sync(0xffffffffu, mx0, 1));
        mx0 = fmaxf(mx0, __shfl_xor_sync(0xffffffffu, mx0, 2));
        mx1 = fmaxf(mx1, __shfl_xor_sync(0xffffffffu, mx1, 1));
        mx1 = fmaxf(mx1, __shfl_xor_sync(0xffffffffu, mx1, 2));
        float mn0 = fmaxf(m0, mx0), mn1 = fmaxf(m1, mx1);
        float sc0 = __expf(m0 - mn0), sc1 = __expf(m1 - mn1);

        float sum0 = 0.f, sum1 = 0.f;
        unsigned pf[4][4];
#pragma unroll
        for (int kc = 0; kc < 4; kc++) {
            int j0 = kc * 2, j1 = kc * 2 + 1;
            float e00 = __expf(s[j0][0] - mn0), e01 = __expf(s[j0][1] - mn0);
            float e10 = __expf(s[j0][2] - mn1), e11 = __expf(s[j0][3] - mn1);
            float f00 = __expf(s[j1][0] - mn0), f01 = __expf(s[j1][1] - mn0);
            float f10 = __expf(s[j1][2] - mn1), f11 = __expf(s[j1][3] - mn1);
            sum0 += e00 + e01 + f00 + f01;
            sum1 += e10 + e11 + f10 + f11;
            pf[kc][0] = h2pack(e00, e01);
            pf[kc][1] = h2pack(e10, e11);
            pf[kc][2] = h2pack(f00, f01);
            pf[kc][3] = h2pack(f10, f11);
        }
        sum0 += __shfl_xor_sync(0xffffffffu, sum0, 1);
        sum0 += __shfl_xor_sync(0xffffffffu, sum0, 2);
        sum1 += __shfl_xor_sync(0xffffffffu, sum1, 1);
        sum1 += __shfl_xor_sync(0xffffffffu, sum1, 2);
        l0 = l0 * sc0 + sum0;
        l1 = l1 * sc1 + sum1;
        m0 = mn0; m1 = mn1;

#pragma unroll
        for (int j = 0; j < 8; j++) {
            o[j][0] *= sc0; o[j][1] *= sc0;
            o[j][2] *= sc1; o[j][3] *= sc1;
        }

#pragma unroll
        for (int kc = 0; kc < 4; kc++) {
            unsigned vf[8][2];
#pragma unroll
            for (int ntp = 0; ntp < 4; ntp++) {
                ldsm_x4_t(vf[ntp * 2][0], vf[ntp * 2][1], vf[ntp * 2 + 1][0], vf[ntp * 2 + 1][1],
                          &Vh[(kc * 16 + v_r) * AT_STR + ntp * 16 + v_c]);
            }
#pragma unroll
            for (int j = 0; j < 8; j++)
                mma_f16(o[j], pf[kc], vf[j]);
        }
    }

    const int tq0 = t0 + wid * 16 + gid;
    const int tq1 = tq0 + 8;
    const float inv0 = (tq0 < len) ? (1.f / l0) : 0.f;
    const float inv1 = (tq1 < len) ? (1.f / l1) : 0.f;
#pragma unroll
    for (int j = 0; j < 8; j++) {
        int col = h * DH + j * 8 + tig * 2;
        *reinterpret_cast<__half2*>(&aout[(btb + tq0) * DD + col]) =
            __floats2half2_rn(o[j][0] * inv0, o[j][1] * inv0);
        *reinterpret_cast<__half2*>(&aout[(btb + tq1) * DD + col]) =
            __floats2half2_rn(o[j][2] * inv1, o[j][3] * inv1);
    }
}

// ---------------- residual + LN + mask; r is 2-partial split-K sum --------------
__global__ __launch_bounds__(256)
void ln_kernel(const float* __restrict__ a, const float* __restrict__ r,
               const float* __restrict__ g, const float* __restrict__ beta,
               const int* __restrict__ lengths, float* __restrict__ out,
               __half* __restrict__ outh, int write_h)
{
    const int row = blockIdx.x;
    const int t = row & (TT - 1);
    const int bi = row >> 11;
    const float maskv = (t < lengths[bi]) ? 1.f : 0.f;
    const float* pa  = a + (size_t)row * DD;
    const float* pr  = r + (size_t)row * DD;
    const float* pr2 = r + (size_t)BT * DD + (size_t)row * DD;

    float s = 0.f, s2 = 0.f;
    for (int i = threadIdx.x; i < DD; i += 256) {
        float v = pa[i] + pr[i] + pr2[i];
        s += v; s2 += v * v;
    }
#pragma unroll
    for (int o = 16; o; o >>= 1) {
        s  += __shfl_down_sync(0xffffffffu, s,  o);
        s2 += __shfl_down_sync(0xffffffffu, s2, o);
    }
    __shared__ float ws[8], ws2[8];
    int w = threadIdx.x >> 5, lane = threadIdx.x & 31;
    if (lane == 0) { ws[w] = s; ws2[w] = s2; }
    __syncthreads();
    if (threadIdx.x == 0) {
        float S = 0.f, S2 = 0.f;
        for (int i = 0; i < 8; i++) { S += ws[i]; S2 += ws2[i]; }
        ws[0] = S; ws2[0] = S2;
    }
    __syncthreads();
    const float mu = ws[0] * (1.f / DD);
    const float var = ws2[0] * (1.f / DD) - mu * mu;
    const float rstd = rsqrtf(var + 1e-5f);
    for (int i = threadIdx.x; i < DD; i += 256) {
        float v = pa[i] + pr[i] + pr2[i];
        float y = ((v - mu) * rstd * g[i] + beta[i]) * maskv;
        out[(size_t)row * DD + i] = y;
        if (write_h) outh[(size_t)row * DD + i] = __float2half(y);
    }
}

// ---------------- launcher ------------------------------------------------------
extern "C" void kernel_launch(void* const* d_in, const int* in_sizes, int n_in,
                              void* d_out, int out_size)
{
    const float* x      = (const float*)d_in[0];
    const int*   lens   = (const int*)  d_in[1];
    const float* w_qkv  = (const float*)d_in[2];
    const float* b_qkv  = (const float*)d_in[3];
    const float* w_proj = (const float*)d_in[4];
    const float* b_proj = (const float*)d_in[5];
    const float* ln1_g  = (const float*)d_in[6];
    const float* ln1_b  = (const float*)d_in[7];
    const float* w_fc   = (const float*)d_in[8];
    const float* b_fc   = (const float*)d_in[9];
    const float* w_out  = (const float*)d_in[10];
    const float* b_out  = (const float*)d_in[11];
    const float* ln2_g  = (const float*)d_in[12];
    const float* ln2_b  = (const float*)d_in[13];
    float* out = (float*)d_out;

    float  *p_proj, *p_n, *p_m;
    __half *p_xh, *p_qkvh, *p_attnh, *p_nh, *p_h1h;
    __half *p_wqkvh, *p_wprojh, *p_wfch, *p_wouth;
    cudaGetSymbolAddress((void**)&p_proj, g_proj);
    cudaGetSymbolAddress((void**)&p_n,    g_n);
    cudaGetSymbolAddress((void**)&p_m,    g_m);
    cudaGetSymbolAddress((void**)&p_xh,    g_xh);
    cudaGetSymbolAddress((void**)&p_qkvh,  g_qkvh);
    cudaGetSymbolAddress((void**)&p_attnh, g_attnh);
    cudaGetSymbolAddress((void**)&p_nh,    g_nh);
    cudaGetSymbolAddress((void**)&p_h1h,   g_h1h);
    cudaGetSymbolAddress((void**)&p_wqkvh,  g_wqkvh);
    cudaGetSymbolAddress((void**)&p_wprojh, g_wprojh);
    cudaGetSymbolAddress((void**)&p_wfch,   g_wfch);
    cudaGetSymbolAddress((void**)&p_wouth,  g_wouth);

    cudaFuncSetAttribute(gemm_h, cudaFuncAttributeMaxDynamicSharedMemorySize, GEMMH_SMEM);
    cudaFuncSetAttribute(attn_h, cudaFuncAttributeMaxDynamicSharedMemorySize, AT_SMEM);

    // 0) fused fp32->fp16 converts (weights + x), one launch
    conv_all<<<CV4 / 256, 256>>>(w_qkv, w_proj, w_fc, w_out, x,
                                 p_wqkvh, p_wprojh, p_wfch, p_wouth, p_xh);

    // 1) qkv = x @ w_qkv + b_qkv                [4096, 2304] fp16
    gemm_h<<<dim3(2304 / 128, BT / 64, 1), 128, GEMMH_SMEM>>>(
        p_xh, p_wqkvh, b_qkv, p_qkvh, lens, BT, 2304, DD, DD, 0, 1);

    // 2) attention (fp16 MMA, register softmax)  [4096, 768] fp16
    attn_h<<<dim3(TT / 128, HH, BB), 256, AT_SMEM>>>(p_qkvh, lens, p_attnh);

    // 3) proj = attn @ w_proj (split-K=2, 2 fp32 partials)
    gemm_h<<<dim3(DD / 128, BT / 64, 2), 128, GEMMH_SMEM>>>(
        p_attnh, p_wprojh, b_proj, p_proj, lens, BT, DD, DD / 2, DD, 0, 0);

    // 4) n = LN(x + proj0 + proj1) * mask  (+ fp16 twin)
    ln_kernel<<<BT, 256>>>(x, p_proj, ln1_g, ln1_b, lens, p_n, p_nh, 1);

    // 5) h1 = gelu(n @ w_fc + b_fc)             [4096, 3072] fp16
    gemm_h<<<dim3(3072 / 128, BT / 64, 1), 128, GEMMH_SMEM>>>(
        p_nh, p_wfch, b_fc, p_h1h, lens, BT, 3072, DD, DD, 1, 1);

    // 6) m = h1 @ w_out (split-K=2, 2 fp32 partials)
    gemm_h<<<dim3(DD / 128, BT / 64, 2), 128, GEMMH_SMEM>>>(
        p_h1h, p_wouth, b_out, p_m, lens, BT, DD, 3072 / 2, 3072, 0, 0);

    // 7) out = LN(n + m0 + m1) * mask
    ln_kernel<<<BT, 256>>>(p_n, p_m, ln2_g, ln2_b, lens, out, p_nh, 0);
}